// round 2
// baseline (speedup 1.0000x reference)
#include <cuda_runtime.h>
#include <cstdint>

#define B_SZ    8
#define L_SEQ   4096
#define D_MODEL 512
#define D_INNER 1024
#define NHEADS  16
#define HEADDIM 64
#define D_STATE 16
#define CONV_DIM 1056
#define D_IN_PROJ 2096
#define BL      (B_SZ * L_SEQ)

// ---------------- scratch (device globals; no allocation allowed) ----------------
__device__ float g_zx[(size_t)BL * D_IN_PROJ];    // in_proj output (reused per direction)
__device__ float g_conv[(size_t)BL * CONV_DIM];   // conv+silu output
__device__ float g_dt[(size_t)BL * NHEADS];       // softplus(dt)
__device__ float g_y[(size_t)BL * D_INNER];       // scan output -> gated/normalized in place
__device__ float g_dirout[(size_t)BL * D_INNER];  // [fwd(512) | bwd(512)] per row, natural time
__device__ float g_pre[(size_t)BL * D_MODEL];     // pre-layernorm

// ---------------- generic fp32 GEMM: C = A[M,K] @ W[N,K]^T (+bias +resid) --------
// flipA: read A rows time-reversed within each batch; flipC: write C rows reversed.
#define BM 128
#define BN 128
#define BKK 16

__global__ void __launch_bounds__(256)
gemm_tn(const float* __restrict__ A, int lda,
        const float* __restrict__ W,
        float* __restrict__ C, int ldc, int ccol,
        int N, int K, int flipA, int flipC,
        const float* __restrict__ bias,
        const float* __restrict__ resid)
{
    __shared__ float As[BKK][BM + 4];
    __shared__ float Ws[BKK][BN + 4];
    const int tid = threadIdx.x;
    const int m0 = blockIdx.y * BM;
    const int n0 = blockIdx.x * BN;

    const int lrow = tid >> 2;        // 0..63
    const int kc   = (tid & 3) << 2;  // 0,4,8,12

    int r0 = m0 + lrow, r1 = r0 + 64;
    int ar0 = flipA ? ((r0 & ~(L_SEQ - 1)) | ((L_SEQ - 1) - (r0 & (L_SEQ - 1)))) : r0;
    int ar1 = flipA ? ((r1 & ~(L_SEQ - 1)) | ((L_SEQ - 1) - (r1 & (L_SEQ - 1)))) : r1;
    const float* Ap0 = A + (size_t)ar0 * lda + kc;
    const float* Ap1 = A + (size_t)ar1 * lda + kc;

    const int wr0 = n0 + lrow, wr1 = wr0 + 64;
    const bool wv0 = wr0 < N, wv1 = wr1 < N;
    const float* Wp0 = W + (size_t)wr0 * K + kc;
    const float* Wp1 = W + (size_t)wr1 * K + kc;

    const int tn = (tid & 15) << 3;
    const int tm = (tid >> 4) << 3;

    float acc[8][8];
    #pragma unroll
    for (int i = 0; i < 8; i++)
        #pragma unroll
        for (int j = 0; j < 8; j++) acc[i][j] = 0.f;

    for (int k0 = 0; k0 < K; k0 += BKK) {
        float4 a0 = *(const float4*)(Ap0 + k0);
        float4 a1 = *(const float4*)(Ap1 + k0);
        float4 w0 = wv0 ? *(const float4*)(Wp0 + k0) : make_float4(0.f, 0.f, 0.f, 0.f);
        float4 w1 = wv1 ? *(const float4*)(Wp1 + k0) : make_float4(0.f, 0.f, 0.f, 0.f);
        __syncthreads();
        As[kc + 0][lrow] = a0.x; As[kc + 1][lrow] = a0.y;
        As[kc + 2][lrow] = a0.z; As[kc + 3][lrow] = a0.w;
        As[kc + 0][lrow + 64] = a1.x; As[kc + 1][lrow + 64] = a1.y;
        As[kc + 2][lrow + 64] = a1.z; As[kc + 3][lrow + 64] = a1.w;
        Ws[kc + 0][lrow] = w0.x; Ws[kc + 1][lrow] = w0.y;
        Ws[kc + 2][lrow] = w0.z; Ws[kc + 3][lrow] = w0.w;
        Ws[kc + 0][lrow + 64] = w1.x; Ws[kc + 1][lrow + 64] = w1.y;
        Ws[kc + 2][lrow + 64] = w1.z; Ws[kc + 3][lrow + 64] = w1.w;
        __syncthreads();
        #pragma unroll
        for (int kk = 0; kk < BKK; kk++) {
            float ra[8], rw[8];
            *(float4*)(ra)     = *(const float4*)(&As[kk][tm]);
            *(float4*)(ra + 4) = *(const float4*)(&As[kk][tm + 4]);
            *(float4*)(rw)     = *(const float4*)(&Ws[kk][tn]);
            *(float4*)(rw + 4) = *(const float4*)(&Ws[kk][tn + 4]);
            #pragma unroll
            for (int i = 0; i < 8; i++)
                #pragma unroll
                for (int j = 0; j < 8; j++)
                    acc[i][j] += ra[i] * rw[j];
        }
    }

    #pragma unroll
    for (int i = 0; i < 8; i++) {
        int r = m0 + tm + i;
        int cr = flipC ? ((r & ~(L_SEQ - 1)) | ((L_SEQ - 1) - (r & (L_SEQ - 1)))) : r;
        float* cp = C + (size_t)cr * ldc + ccol;
        const float* rp = resid + (size_t)cr * ldc + ccol;  // only deref'd if resid != null
        #pragma unroll
        for (int j = 0; j < 8; j++) {
            int n = n0 + tn + j;
            if (n < N) {
                float v = acc[i][j];
                if (bias)  v += bias[n];
                if (resid) v += rp[n];
                cp[n] = v;
            }
        }
    }
}

// ---------------- causal depthwise conv (K=4) + SiLU, plus softplus(dt) ----------
__global__ void conv_silu_kernel(const float* __restrict__ conv_w,
                                 const float* __restrict__ conv_b,
                                 const float* __restrict__ dt_bias)
{
    const int row = blockIdx.x;
    const int l = row & (L_SEQ - 1);
    for (int c = threadIdx.x; c < CONV_DIM; c += blockDim.x) {
        float accv = conv_b[c];
        #pragma unroll
        for (int k = 0; k < 4; k++) {
            int ls = l - 3 + k;
            if (ls >= 0) {
                size_t rr = (size_t)(row - 3 + k);
                accv += g_zx[rr * D_IN_PROJ + D_INNER + c] * conv_w[c * 4 + k];
            }
        }
        g_conv[(size_t)row * CONV_DIM + c] = accv / (1.f + expf(-accv));
    }
    if (threadIdx.x < NHEADS) {
        int h = threadIdx.x;
        float rawv = g_zx[(size_t)row * D_IN_PROJ + D_INNER + CONV_DIM + h] + dt_bias[h];
        float sp = (rawv > 20.f) ? rawv : log1pf(expf(rawv));
        g_dt[(size_t)row * NHEADS + h] = sp;
    }
}

// ---------------- selective scan: one CTA per (b, h), state in registers --------
#define TS 64
__global__ void __launch_bounds__(256)
scan_kernel(const float* __restrict__ A_log, const float* __restrict__ Dp)
{
    const int h = blockIdx.x, b = blockIdx.y;
    const int tid = threadIdx.x;
    const int p = tid >> 2, q = tid & 3;
    const float Aneg = -expf(A_log[h]);
    const float Dh = Dp[h];

    __shared__ float sx[TS][64];
    __shared__ float sB[TS][16];
    __shared__ float sC[TS][16];
    __shared__ float sdt[TS];
    __shared__ float sdA[TS];
    __shared__ float sy[TS][64];

    float hst[4] = {0.f, 0.f, 0.f, 0.f};
    const size_t rowbase = (size_t)b * L_SEQ;

    for (int t0 = 0; t0 < L_SEQ; t0 += TS) {
        __syncthreads();
        for (int idx = tid; idx < TS * 64; idx += 256) {
            int s = idx >> 6, pp = idx & 63;
            sx[s][pp] = g_conv[(rowbase + t0 + s) * CONV_DIM + h * 64 + pp];
        }
        for (int idx = tid; idx < TS * 16; idx += 256) {
            int s = idx >> 4, n = idx & 15;
            size_t rb = (rowbase + t0 + s) * CONV_DIM + D_INNER;
            sB[s][n] = g_conv[rb + n];
            sC[s][n] = g_conv[rb + D_STATE + n];
        }
        if (tid < TS) {
            float dtv = g_dt[(rowbase + t0 + tid) * NHEADS + h];
            sdt[tid] = dtv;
            sdA[tid] = expf(dtv * Aneg);
        }
        __syncthreads();
        for (int s = 0; s < TS; s++) {
            float dA = sdA[s];
            float xv = sx[s][p];
            float coef = sdt[s] * xv;
            float4 Bv = *(const float4*)&sB[s][q * 4];
            float4 Cv = *(const float4*)&sC[s][q * 4];
            hst[0] = hst[0] * dA + coef * Bv.x;
            hst[1] = hst[1] * dA + coef * Bv.y;
            hst[2] = hst[2] * dA + coef * Bv.z;
            hst[3] = hst[3] * dA + coef * Bv.w;
            float yp = hst[0] * Cv.x + hst[1] * Cv.y + hst[2] * Cv.z + hst[3] * Cv.w;
            yp += __shfl_xor_sync(0xffffffffu, yp, 1);
            yp += __shfl_xor_sync(0xffffffffu, yp, 2);
            if (q == 0) sy[s][p] = yp + Dh * xv;
        }
        __syncthreads();
        for (int idx = tid; idx < TS * 64; idx += 256) {
            int s = idx >> 6, pp = idx & 63;
            g_y[(rowbase + t0 + s) * D_INNER + h * 64 + pp] = sy[s][pp];
        }
    }
}

// ---------------- y *= silu(z); RMSNorm(y) * norm_w  (in place) ------------------
__global__ void gate_rms_kernel(const float* __restrict__ norm_w)
{
    const int row = blockIdx.x, tid = threadIdx.x;
    const size_t yb = (size_t)row * D_INNER;
    const size_t zb = (size_t)row * D_IN_PROJ;
    float v[4];
    float ss = 0.f;
    #pragma unroll
    for (int j = 0; j < 4; j++) {
        int c = j * 256 + tid;
        float yv = g_y[yb + c];
        float z = g_zx[zb + c];
        yv *= z / (1.f + expf(-z));
        v[j] = yv;
        ss += yv * yv;
    }
    __shared__ float red[8];
    #pragma unroll
    for (int o = 16; o > 0; o >>= 1) ss += __shfl_xor_sync(0xffffffffu, ss, o);
    if ((tid & 31) == 0) red[tid >> 5] = ss;
    __syncthreads();
    float tot = red[0] + red[1] + red[2] + red[3] + red[4] + red[5] + red[6] + red[7];
    float sc = rsqrtf(tot * (1.f / D_INNER) + 1e-5f);
    #pragma unroll
    for (int j = 0; j < 4; j++) {
        int c = j * 256 + tid;
        g_y[yb + c] = v[j] * sc * norm_w[c];
    }
}

// ---------------- final LayerNorm over 512 -> d_out ------------------------------
__global__ void ln_kernel(const float* __restrict__ ln_w, const float* __restrict__ ln_b,
                          float* __restrict__ out)
{
    const int row = blockIdx.x, tid = threadIdx.x;  // 128 threads
    const size_t base = (size_t)row * D_MODEL;
    float v[4];
    float s = 0.f, s2 = 0.f;
    #pragma unroll
    for (int j = 0; j < 4; j++) {
        int c = j * 128 + tid;
        float xv = g_pre[base + c];
        v[j] = xv;
        s += xv;
        s2 += xv * xv;
    }
    __shared__ float rs[4], rs2[4];
    #pragma unroll
    for (int o = 16; o > 0; o >>= 1) {
        s  += __shfl_xor_sync(0xffffffffu, s, o);
        s2 += __shfl_xor_sync(0xffffffffu, s2, o);
    }
    if ((tid & 31) == 0) { rs[tid >> 5] = s; rs2[tid >> 5] = s2; }
    __syncthreads();
    float ts = rs[0] + rs[1] + rs[2] + rs[3];
    float ts2 = rs2[0] + rs2[1] + rs2[2] + rs2[3];
    float mu = ts * (1.f / D_MODEL);
    float var = ts2 * (1.f / D_MODEL) - mu * mu;
    float isd = rsqrtf(var + 1e-5f);
    #pragma unroll
    for (int j = 0; j < 4; j++) {
        int c = j * 128 + tid;
        out[base + c] = (v[j] - mu) * isd * ln_w[c] + ln_b[c];
    }
}

// ---------------- orchestration ---------------------------------------------------
extern "C" void kernel_launch(void* const* d_in, const int* in_sizes, int n_in,
                              void* d_out, int out_size)
{
    const float* x      = (const float*)d_in[0];
    const float* proj_w = (const float*)d_in[17];
    const float* proj_b = (const float*)d_in[18];
    const float* ln_w   = (const float*)d_in[19];
    const float* ln_b   = (const float*)d_in[20];

    float *zx, *yb, *dirout, *pre;
    cudaGetSymbolAddress((void**)&zx, g_zx);
    cudaGetSymbolAddress((void**)&yb, g_y);
    cudaGetSymbolAddress((void**)&dirout, g_dirout);
    cudaGetSymbolAddress((void**)&pre, g_pre);

    for (int dir = 0; dir < 2; dir++) {
        const float* in_proj  = (const float*)d_in[1 + 8 * dir + 0];
        const float* conv_w   = (const float*)d_in[1 + 8 * dir + 1];
        const float* conv_b   = (const float*)d_in[1 + 8 * dir + 2];
        const float* dt_bias  = (const float*)d_in[1 + 8 * dir + 3];
        const float* A_log    = (const float*)d_in[1 + 8 * dir + 4];
        const float* Dp       = (const float*)d_in[1 + 8 * dir + 5];
        const float* norm_w   = (const float*)d_in[1 + 8 * dir + 6];
        const float* out_proj = (const float*)d_in[1 + 8 * dir + 7];

        // zxbcdt = x(dir-flipped) @ in_proj^T  : [BL, 2096]
        gemm_tn<<<dim3((D_IN_PROJ + BN - 1) / BN, BL / BM), 256>>>(
            x, D_MODEL, in_proj, zx, D_IN_PROJ, 0,
            D_IN_PROJ, D_MODEL, dir, 0, nullptr, nullptr);

        // conv + silu + softplus(dt)
        conv_silu_kernel<<<BL, 256>>>(conv_w, conv_b, dt_bias);

        // selective scan (+ D*x skip)
        scan_kernel<<<dim3(NHEADS, B_SZ), 256>>>(A_log, Dp);

        // y *= silu(z); RMSNorm * norm_w
        gate_rms_kernel<<<BL, 256>>>(norm_w);

        // x_dir = y @ out_proj^T, written into half of g_dirout, time-unflipped for bwd
        gemm_tn<<<dim3(D_MODEL / BN, BL / BM), 256>>>(
            yb, D_INNER, out_proj, dirout, D_INNER, dir * D_MODEL,
            D_MODEL, D_INNER, 0, dir, nullptr, nullptr);
    }

    // pre = x + proj_b + [fwd|bwd] @ proj_w^T
    gemm_tn<<<dim3(D_MODEL / BN, BL / BM), 256>>>(
        dirout, D_INNER, proj_w, pre, D_MODEL, 0,
        D_MODEL, D_INNER, 0, 0, proj_b, x);

    // layernorm -> output
    ln_kernel<<<BL, 128>>>(ln_w, ln_b, (float*)d_out);
}

// round 3
// speedup vs baseline: 1.7742x; 1.7742x over previous
#include <cuda_runtime.h>
#include <cstdint>

#define B_SZ    8
#define L_SEQ   4096
#define D_MODEL 512
#define D_INNER 1024
#define NHEADS  16
#define HEADDIM 64
#define D_STATE 16
#define CONV_DIM 1056
#define D_IN_PROJ 2096
#define BL      (B_SZ * L_SEQ)

// ---------------- scratch (device globals; no allocation allowed) ----------------
__device__ float g_zx[(size_t)BL * D_IN_PROJ];    // in_proj output (reused per direction)
__device__ float g_conv[(size_t)BL * CONV_DIM];   // conv+silu output
__device__ float g_dt[(size_t)BL * NHEADS];       // softplus(dt)
__device__ float g_y[(size_t)BL * D_INNER];       // scan output -> gated/normalized in place
__device__ float g_dirout[(size_t)BL * D_INNER];  // [fwd(512) | bwd(512)] per row, natural time
__device__ float g_pre[(size_t)BL * D_MODEL];     // pre-layernorm

__device__ __forceinline__ unsigned f2tf(float f) {
    unsigned u;
    asm("cvt.rna.tf32.f32 %0, %1;" : "=r"(u) : "f"(f));
    return u;
}

__device__ __forceinline__ int fliprow(int r) {
    return (r & ~(L_SEQ - 1)) | ((L_SEQ - 1) - (r & (L_SEQ - 1)));
}

// ---------------- tf32 tensor-core GEMM: C = A[M,K] @ W[N,K]^T (+bias +resid) ----
// BM=128, BN=128, BK=32; 8 warps as 2(m) x 4(n); warp tile 64x32; mma m16n8k8.
// Double-buffered smem (2 x 32KB), register-staged loads with cvt.rna to tf32,
// XOR-swizzled smem layout for conflict-free ldmatrix.
#define GKT_BK 32

__global__ void __launch_bounds__(256)
gemm_tf32(const float* __restrict__ A, int lda,
          const float* __restrict__ W,
          float* __restrict__ C, int ldc, int ccol,
          int N, int K, int flipA, int flipC,
          const float* __restrict__ bias,
          const float* __restrict__ resid)
{
    extern __shared__ char smem[];
    const uint32_t sbase = (uint32_t)__cvta_generic_to_shared(smem);

    const int tid = threadIdx.x;
    const int l   = tid & 31;
    const int w   = tid >> 5;
    const int wm  = w >> 2;   // 0..1
    const int wn  = w & 3;    // 0..3
    const int m0  = blockIdx.y * 128;
    const int n0  = blockIdx.x * 128;

    // ---- fragment smem address precompute (A) ----
    int aRB[4], aRX[4];
    const int ahc = (l >> 4) & 1;            // k-chunk selector for A ldmatrix
    #pragma unroll
    for (int mi = 0; mi < 4; mi++) {
        int ar = wm * 64 + mi * 16 + ((l >> 3) & 1) * 8 + (l & 7);
        aRB[mi] = ar * 128;
        aRX[mi] = ar & 7;
    }
    // ---- fragment smem address precompute (B) ----
    int bRB[2], bRX[2];
    const int bkc = (l >> 3) & 1;            // k-chunk selector for B ldmatrix
    #pragma unroll
    for (int p = 0; p < 2; p++) {
        int br = wn * 32 + p * 16 + ((l >> 4) & 1) * 8 + (l & 7);
        bRB[p] = br * 128;
        bRX[p] = br & 7;
    }

    // ---- load/store-stage index precompute ----
    int srow[4], sch[4], swoff[4];
    #pragma unroll
    for (int i = 0; i < 4; i++) {
        int q = tid + i * 256;
        srow[i]  = q >> 3;
        sch[i]   = q & 7;
        swoff[i] = srow[i] * 128 + ((sch[i] ^ (srow[i] & 7)) << 4);
    }

    float acc[4][4][4];
    #pragma unroll
    for (int mi = 0; mi < 4; mi++)
        #pragma unroll
        for (int ni = 0; ni < 4; ni++)
            #pragma unroll
            for (int k = 0; k < 4; k++) acc[mi][ni][k] = 0.f;

    uint4 aS[4], bS[4];

    auto ldg = [&](int kt) {
        const int k0 = kt * GKT_BK;
        #pragma unroll
        for (int i = 0; i < 4; i++) {
            int r = m0 + srow[i];
            int ar = flipA ? fliprow(r) : r;
            float4 v = *(const float4*)(A + (size_t)ar * lda + k0 + sch[i] * 4);
            aS[i] = make_uint4(f2tf(v.x), f2tf(v.y), f2tf(v.z), f2tf(v.w));
            int n = n0 + srow[i];
            float4 wv = (n < N) ? *(const float4*)(W + (size_t)n * K + k0 + sch[i] * 4)
                                : make_float4(0.f, 0.f, 0.f, 0.f);
            bS[i] = make_uint4(f2tf(wv.x), f2tf(wv.y), f2tf(wv.z), f2tf(wv.w));
        }
    };
    auto sts = [&](int s) {
        char* sp = smem + s * 32768;
        #pragma unroll
        for (int i = 0; i < 4; i++) {
            *(uint4*)(sp + swoff[i])         = aS[i];
            *(uint4*)(sp + 16384 + swoff[i]) = bS[i];
        }
    };
    auto compute = [&](int s) {
        const uint32_t Ab = sbase + s * 32768;
        const uint32_t Bb = Ab + 16384;
        #pragma unroll
        for (int ks = 0; ks < 4; ks++) {
            uint32_t af[4][4];
            #pragma unroll
            for (int mi = 0; mi < 4; mi++) {
                uint32_t ad = Ab + aRB[mi] + ((((ks << 1) + ahc) ^ aRX[mi]) << 4);
                asm volatile("ldmatrix.sync.aligned.m8n8.x4.shared.b16 {%0,%1,%2,%3}, [%4];"
                    : "=r"(af[mi][0]), "=r"(af[mi][1]), "=r"(af[mi][2]), "=r"(af[mi][3])
                    : "r"(ad));
            }
            uint32_t bf[4][2];
            #pragma unroll
            for (int p = 0; p < 2; p++) {
                uint32_t bd = Bb + bRB[p] + ((((ks << 1) + bkc) ^ bRX[p]) << 4);
                uint32_t q0, q1, q2, q3;
                asm volatile("ldmatrix.sync.aligned.m8n8.x4.shared.b16 {%0,%1,%2,%3}, [%4];"
                    : "=r"(q0), "=r"(q1), "=r"(q2), "=r"(q3) : "r"(bd));
                bf[2 * p][0] = q0; bf[2 * p][1] = q1;
                bf[2 * p + 1][0] = q2; bf[2 * p + 1][1] = q3;
            }
            #pragma unroll
            for (int mi = 0; mi < 4; mi++)
                #pragma unroll
                for (int ni = 0; ni < 4; ni++) {
                    asm volatile(
                        "mma.sync.aligned.m16n8k8.row.col.f32.tf32.tf32.f32 "
                        "{%0,%1,%2,%3},{%4,%5,%6,%7},{%8,%9},{%0,%1,%2,%3};"
                        : "+f"(acc[mi][ni][0]), "+f"(acc[mi][ni][1]),
                          "+f"(acc[mi][ni][2]), "+f"(acc[mi][ni][3])
                        : "r"(af[mi][0]), "r"(af[mi][1]), "r"(af[mi][2]), "r"(af[mi][3]),
                          "r"(bf[ni][0]), "r"(bf[ni][1]));
                }
        }
    };

    const int KT = K / GKT_BK;
    ldg(0);
    sts(0);
    for (int kt = 0; kt < KT; kt++) {
        __syncthreads();
        if (kt + 1 < KT) ldg(kt + 1);
        compute(kt & 1);
        if (kt + 1 < KT) sts((kt + 1) & 1);
    }

    // ---- epilogue ----
    #pragma unroll
    for (int mi = 0; mi < 4; mi++) {
        #pragma unroll
        for (int half = 0; half < 2; half++) {
            int r = m0 + wm * 64 + mi * 16 + (l >> 2) + half * 8;
            int cr = flipC ? fliprow(r) : r;
            float* cp = C + (size_t)cr * ldc + ccol;
            const float* rp = resid + (size_t)cr * ldc + ccol;
            #pragma unroll
            for (int ni = 0; ni < 4; ni++) {
                int col = n0 + wn * 32 + ni * 8 + ((l & 3) << 1);
                if (col < N) {
                    float v0 = acc[mi][ni][half * 2 + 0];
                    float v1 = acc[mi][ni][half * 2 + 1];
                    if (bias)  { v0 += bias[col]; v1 += bias[col + 1]; }
                    if (resid) { v0 += rp[col];   v1 += rp[col + 1]; }
                    float2 o = make_float2(v0, v1);
                    *(float2*)(cp + col) = o;
                }
            }
        }
    }
}

// ---------------- causal depthwise conv (K=4) + SiLU, plus softplus(dt) ----------
__global__ void conv_silu_kernel(const float* __restrict__ conv_w,
                                 const float* __restrict__ conv_b,
                                 const float* __restrict__ dt_bias)
{
    const int row = blockIdx.x;
    const int l = row & (L_SEQ - 1);
    for (int c = threadIdx.x; c < CONV_DIM; c += blockDim.x) {
        float accv = conv_b[c];
        #pragma unroll
        for (int k = 0; k < 4; k++) {
            int ls = l - 3 + k;
            if (ls >= 0) {
                size_t rr = (size_t)(row - 3 + k);
                accv += g_zx[rr * D_IN_PROJ + D_INNER + c] * conv_w[c * 4 + k];
            }
        }
        g_conv[(size_t)row * CONV_DIM + c] = accv / (1.f + expf(-accv));
    }
    if (threadIdx.x < NHEADS) {
        int h = threadIdx.x;
        float rawv = g_zx[(size_t)row * D_IN_PROJ + D_INNER + CONV_DIM + h] + dt_bias[h];
        float sp = (rawv > 20.f) ? rawv : log1pf(expf(rawv));
        g_dt[(size_t)row * NHEADS + h] = sp;
    }
}

// ---------------- selective scan: one CTA per (b, h), state in registers --------
#define TS 64
__global__ void __launch_bounds__(256)
scan_kernel(const float* __restrict__ A_log, const float* __restrict__ Dp)
{
    const int h = blockIdx.x, b = blockIdx.y;
    const int tid = threadIdx.x;
    const int p = tid >> 2, q = tid & 3;
    const float Aneg = -expf(A_log[h]);
    const float Dh = Dp[h];

    __shared__ float sx[TS][64];
    __shared__ float sB[TS][16];
    __shared__ float sC[TS][16];
    __shared__ float sdt[TS];
    __shared__ float sdA[TS];
    __shared__ float sy[TS][64];

    float hst[4] = {0.f, 0.f, 0.f, 0.f};
    const size_t rowbase = (size_t)b * L_SEQ;

    for (int t0 = 0; t0 < L_SEQ; t0 += TS) {
        __syncthreads();
        for (int idx = tid; idx < TS * 64; idx += 256) {
            int s = idx >> 6, pp = idx & 63;
            sx[s][pp] = g_conv[(rowbase + t0 + s) * CONV_DIM + h * 64 + pp];
        }
        for (int idx = tid; idx < TS * 16; idx += 256) {
            int s = idx >> 4, n = idx & 15;
            size_t rb = (rowbase + t0 + s) * CONV_DIM + D_INNER;
            sB[s][n] = g_conv[rb + n];
            sC[s][n] = g_conv[rb + D_STATE + n];
        }
        if (tid < TS) {
            float dtv = g_dt[(rowbase + t0 + tid) * NHEADS + h];
            sdt[tid] = dtv;
            sdA[tid] = expf(dtv * Aneg);
        }
        __syncthreads();
        for (int s = 0; s < TS; s++) {
            float dA = sdA[s];
            float xv = sx[s][p];
            float coef = sdt[s] * xv;
            float4 Bv = *(const float4*)&sB[s][q * 4];
            float4 Cv = *(const float4*)&sC[s][q * 4];
            hst[0] = hst[0] * dA + coef * Bv.x;
            hst[1] = hst[1] * dA + coef * Bv.y;
            hst[2] = hst[2] * dA + coef * Bv.z;
            hst[3] = hst[3] * dA + coef * Bv.w;
            float yp = hst[0] * Cv.x + hst[1] * Cv.y + hst[2] * Cv.z + hst[3] * Cv.w;
            yp += __shfl_xor_sync(0xffffffffu, yp, 1);
            yp += __shfl_xor_sync(0xffffffffu, yp, 2);
            if (q == 0) sy[s][p] = yp + Dh * xv;
        }
        __syncthreads();
        for (int idx = tid; idx < TS * 64; idx += 256) {
            int s = idx >> 6, pp = idx & 63;
            g_y[(rowbase + t0 + s) * D_INNER + h * 64 + pp] = sy[s][pp];
        }
    }
}

// ---------------- y *= silu(z); RMSNorm(y) * norm_w  (in place) ------------------
__global__ void gate_rms_kernel(const float* __restrict__ norm_w)
{
    const int row = blockIdx.x, tid = threadIdx.x;
    const size_t yb = (size_t)row * D_INNER;
    const size_t zb = (size_t)row * D_IN_PROJ;
    float v[4];
    float ss = 0.f;
    #pragma unroll
    for (int j = 0; j < 4; j++) {
        int c = j * 256 + tid;
        float yv = g_y[yb + c];
        float z = g_zx[zb + c];
        yv *= z / (1.f + expf(-z));
        v[j] = yv;
        ss += yv * yv;
    }
    __shared__ float red[8];
    #pragma unroll
    for (int o = 16; o > 0; o >>= 1) ss += __shfl_xor_sync(0xffffffffu, ss, o);
    if ((tid & 31) == 0) red[tid >> 5] = ss;
    __syncthreads();
    float tot = red[0] + red[1] + red[2] + red[3] + red[4] + red[5] + red[6] + red[7];
    float sc = rsqrtf(tot * (1.f / D_INNER) + 1e-5f);
    #pragma unroll
    for (int j = 0; j < 4; j++) {
        int c = j * 256 + tid;
        g_y[yb + c] = v[j] * sc * norm_w[c];
    }
}

// ---------------- final LayerNorm over 512 -> d_out ------------------------------
__global__ void ln_kernel(const float* __restrict__ ln_w, const float* __restrict__ ln_b,
                          float* __restrict__ out)
{
    const int row = blockIdx.x, tid = threadIdx.x;  // 128 threads
    const size_t base = (size_t)row * D_MODEL;
    float v[4];
    float s = 0.f, s2 = 0.f;
    #pragma unroll
    for (int j = 0; j < 4; j++) {
        int c = j * 128 + tid;
        float xv = g_pre[base + c];
        v[j] = xv;
        s += xv;
        s2 += xv * xv;
    }
    __shared__ float rs[4], rs2[4];
    #pragma unroll
    for (int o = 16; o > 0; o >>= 1) {
        s  += __shfl_xor_sync(0xffffffffu, s, o);
        s2 += __shfl_xor_sync(0xffffffffu, s2, o);
    }
    if ((tid & 31) == 0) { rs[tid >> 5] = s; rs2[tid >> 5] = s2; }
    __syncthreads();
    float ts = rs[0] + rs[1] + rs[2] + rs[3];
    float ts2 = rs2[0] + rs2[1] + rs2[2] + rs2[3];
    float mu = ts * (1.f / D_MODEL);
    float var = ts2 * (1.f / D_MODEL) - mu * mu;
    float isd = rsqrtf(var + 1e-5f);
    #pragma unroll
    for (int j = 0; j < 4; j++) {
        int c = j * 128 + tid;
        out[base + c] = (v[j] - mu) * isd * ln_w[c] + ln_b[c];
    }
}

// ---------------- orchestration ---------------------------------------------------
extern "C" void kernel_launch(void* const* d_in, const int* in_sizes, int n_in,
                              void* d_out, int out_size)
{
    const float* x      = (const float*)d_in[0];
    const float* proj_w = (const float*)d_in[17];
    const float* proj_b = (const float*)d_in[18];
    const float* ln_w   = (const float*)d_in[19];
    const float* ln_b   = (const float*)d_in[20];

    float *zx, *yb, *dirout, *pre;
    cudaGetSymbolAddress((void**)&zx, g_zx);
    cudaGetSymbolAddress((void**)&yb, g_y);
    cudaGetSymbolAddress((void**)&dirout, g_dirout);
    cudaGetSymbolAddress((void**)&pre, g_pre);

    const int SMEM = 65536;
    cudaFuncSetAttribute(gemm_tf32, cudaFuncAttributeMaxDynamicSharedMemorySize, SMEM);

    for (int dir = 0; dir < 2; dir++) {
        const float* in_proj  = (const float*)d_in[1 + 8 * dir + 0];
        const float* conv_w   = (const float*)d_in[1 + 8 * dir + 1];
        const float* conv_b   = (const float*)d_in[1 + 8 * dir + 2];
        const float* dt_bias  = (const float*)d_in[1 + 8 * dir + 3];
        const float* A_log    = (const float*)d_in[1 + 8 * dir + 4];
        const float* Dp       = (const float*)d_in[1 + 8 * dir + 5];
        const float* norm_w   = (const float*)d_in[1 + 8 * dir + 6];
        const float* out_proj = (const float*)d_in[1 + 8 * dir + 7];

        // zxbcdt = x(dir-flipped) @ in_proj^T  : [BL, 2096]
        gemm_tf32<<<dim3((D_IN_PROJ + 127) / 128, BL / 128), 256, SMEM>>>(
            x, D_MODEL, in_proj, zx, D_IN_PROJ, 0,
            D_IN_PROJ, D_MODEL, dir, 0, nullptr, nullptr);

        // conv + silu + softplus(dt)
        conv_silu_kernel<<<BL, 256>>>(conv_w, conv_b, dt_bias);

        // selective scan (+ D*x skip)
        scan_kernel<<<dim3(NHEADS, B_SZ), 256>>>(A_log, Dp);

        // y *= silu(z); RMSNorm * norm_w
        gate_rms_kernel<<<BL, 256>>>(norm_w);

        // x_dir = y @ out_proj^T, written into half of g_dirout, time-unflipped for bwd
        gemm_tf32<<<dim3(D_MODEL / 128, BL / 128), 256, SMEM>>>(
            yb, D_INNER, out_proj, dirout, D_INNER, dir * D_MODEL,
            D_MODEL, D_INNER, 0, dir, nullptr, nullptr);
    }

    // pre = x + proj_b + [fwd|bwd] @ proj_w^T
    gemm_tf32<<<dim3(D_MODEL / 128, BL / 128), 256, SMEM>>>(
        dirout, D_INNER, proj_w, pre, D_MODEL, 0,
        D_MODEL, D_INNER, 0, 0, proj_b, x);

    // layernorm -> output
    ln_kernel<<<BL, 128>>>(ln_w, ln_b, (float*)d_out);
}

// round 5
// speedup vs baseline: 2.9261x; 1.6492x over previous
#include <cuda_runtime.h>
#include <cstdint>

#define B_SZ    8
#define L_SEQ   4096
#define D_MODEL 512
#define D_INNER 1024
#define NHEADS  16
#define HEADDIM 64
#define D_STATE 16
#define CONV_DIM 1056
#define D_IN_PROJ 2096
#define BL      (B_SZ * L_SEQ)
#define CS      64
#define NC      (L_SEQ / CS)

// ---------------- scratch (device globals; no allocation allowed) ----------------
__device__ float g_zx[(size_t)BL * D_IN_PROJ];
__device__ float g_conv[(size_t)BL * CONV_DIM];
__device__ float g_dt[(size_t)BL * NHEADS];
__device__ float g_y[(size_t)BL * D_INNER];
__device__ float g_dirout[(size_t)BL * D_INNER];
__device__ float g_pre[(size_t)BL * D_MODEL];
__device__ float g_hstate[(size_t)B_SZ * NHEADS * NC * 1024];
__device__ float g_P[B_SZ * NHEADS * NC];

__device__ __forceinline__ int fliprow(int r) {
    return (r & ~(L_SEQ - 1)) | ((L_SEQ - 1) - (r & (L_SEQ - 1)));
}

__device__ __forceinline__ void cpa16(uint32_t dst, const void* src, int sz) {
    asm volatile("cp.async.cg.shared.global [%0], [%1], 16, %2;"
                 :: "r"(dst), "l"(src), "r"(sz));
}
#define CP_COMMIT() asm volatile("cp.async.commit_group;" ::: "memory")
#define CP_WAIT1()  asm volatile("cp.async.wait_group 1;" ::: "memory")

// ============ tf32 mma.sync GEMM: C = A[M,K] @ W[N,K]^T (+bias +resid) ==========
// 128x128 CTA tile, BK=32, 3-stage cp.async pipeline, 8 warps (2m x 4n), warp
// tile 64x32, mma m16n8k8.tf32 on raw fp32 bits (RZ truncation in HW).
#define GT_STAGES 3
#define GT_SMEM (GT_STAGES * 32768 + 1024)

__global__ void __launch_bounds__(256, 2)
gemm_tf32(const float* __restrict__ A, int lda,
          const float* __restrict__ W,
          float* __restrict__ C, int ldc, int ccol,
          int N, int K, int flipA, int flipC,
          const float* __restrict__ bias,
          const float* __restrict__ resid)
{
    extern __shared__ char dsm[];
    const uint32_t sb_raw = (uint32_t)__cvta_generic_to_shared(dsm);
    const uint32_t sb = (sb_raw + 1023u) & ~1023u;

    const int tid = threadIdx.x;
    const int l   = tid & 31;
    const int w   = tid >> 5;
    const int wm  = w >> 2;
    const int wn  = w & 3;
    const int m0  = blockIdx.y * 128;
    const int n0  = blockIdx.x * 128;

    // ldmatrix fragment address precompute
    int aRB[4], aRX[4];
    const int ahc = (l >> 4) & 1;
    #pragma unroll
    for (int mi = 0; mi < 4; mi++) {
        int ar = wm * 64 + mi * 16 + ((l >> 3) & 1) * 8 + (l & 7);
        aRB[mi] = ar * 128;
        aRX[mi] = ar & 7;
    }
    int bRB[2], bRX[2];
    const int bkc = (l >> 3) & 1;
    #pragma unroll
    for (int p = 0; p < 2; p++) {
        int br = wn * 32 + p * 16 + ((l >> 4) & 1) * 8 + (l & 7);
        bRB[p] = br * 128;
        bRX[p] = br & 7;
    }

    // cp.async stage indices: 4 x 16B per operand per thread
    int srow[4], sch[4], swoff[4], arow[4], wrow[4], wvalid[4];
    #pragma unroll
    for (int i = 0; i < 4; i++) {
        int q = tid + i * 256;
        srow[i] = q >> 3;
        sch[i]  = q & 7;
        swoff[i] = srow[i] * 128 + ((sch[i] ^ (srow[i] & 7)) << 4);
        int r = m0 + srow[i];
        arow[i] = flipA ? fliprow(r) : r;
        int n = n0 + srow[i];
        wvalid[i] = (n < N) ? 16 : 0;
        wrow[i] = (n < N) ? n : 0;
    }

    float acc[4][4][4];
    #pragma unroll
    for (int mi = 0; mi < 4; mi++)
        #pragma unroll
        for (int ni = 0; ni < 4; ni++)
            #pragma unroll
            for (int k = 0; k < 4; k++) acc[mi][ni][k] = 0.f;

    auto issue = [&](int s) {
        const int k0 = s * 32;
        const uint32_t base = sb + (s % GT_STAGES) * 32768;
        #pragma unroll
        for (int i = 0; i < 4; i++) {
            cpa16(base + swoff[i],
                  A + (size_t)arow[i] * lda + k0 + sch[i] * 4, 16);
            cpa16(base + 16384 + swoff[i],
                  W + (size_t)wrow[i] * K + k0 + sch[i] * 4, wvalid[i]);
        }
    };
    auto compute = [&](int s) {
        const uint32_t Ab = sb + s * 32768;
        const uint32_t Bb = Ab + 16384;
        #pragma unroll
        for (int ks = 0; ks < 4; ks++) {
            uint32_t af[4][4];
            #pragma unroll
            for (int mi = 0; mi < 4; mi++) {
                uint32_t ad = Ab + aRB[mi] + ((((ks << 1) + ahc) ^ aRX[mi]) << 4);
                asm volatile("ldmatrix.sync.aligned.m8n8.x4.shared.b16 {%0,%1,%2,%3}, [%4];"
                    : "=r"(af[mi][0]), "=r"(af[mi][1]), "=r"(af[mi][2]), "=r"(af[mi][3])
                    : "r"(ad));
            }
            uint32_t bf[4][2];
            #pragma unroll
            for (int p = 0; p < 2; p++) {
                uint32_t bd = Bb + bRB[p] + ((((ks << 1) + bkc) ^ bRX[p]) << 4);
                uint32_t q0, q1, q2, q3;
                asm volatile("ldmatrix.sync.aligned.m8n8.x4.shared.b16 {%0,%1,%2,%3}, [%4];"
                    : "=r"(q0), "=r"(q1), "=r"(q2), "=r"(q3) : "r"(bd));
                bf[2 * p][0] = q0; bf[2 * p][1] = q1;
                bf[2 * p + 1][0] = q2; bf[2 * p + 1][1] = q3;
            }
            #pragma unroll
            for (int mi = 0; mi < 4; mi++)
                #pragma unroll
                for (int ni = 0; ni < 4; ni++) {
                    asm volatile(
                        "mma.sync.aligned.m16n8k8.row.col.f32.tf32.tf32.f32 "
                        "{%0,%1,%2,%3},{%4,%5,%6,%7},{%8,%9},{%0,%1,%2,%3};"
                        : "+f"(acc[mi][ni][0]), "+f"(acc[mi][ni][1]),
                          "+f"(acc[mi][ni][2]), "+f"(acc[mi][ni][3])
                        : "r"(af[mi][0]), "r"(af[mi][1]), "r"(af[mi][2]), "r"(af[mi][3]),
                          "r"(bf[ni][0]), "r"(bf[ni][1]));
                }
        }
    };

    const int KT = K / 32;
    issue(0); CP_COMMIT();
    issue(1); CP_COMMIT();
    for (int kt = 0; kt < KT; kt++) {
        CP_WAIT1();
        __syncthreads();
        if (kt + 2 < KT) issue(kt + 2);
        CP_COMMIT();
        compute(kt % GT_STAGES);
    }

    // epilogue
    #pragma unroll
    for (int mi = 0; mi < 4; mi++) {
        #pragma unroll
        for (int half = 0; half < 2; half++) {
            int r = m0 + wm * 64 + mi * 16 + (l >> 2) + half * 8;
            int cr = flipC ? fliprow(r) : r;
            float* cp = C + (size_t)cr * ldc + ccol;
            const float* rp = resid + (size_t)cr * ldc + ccol;
            #pragma unroll
            for (int ni = 0; ni < 4; ni++) {
                int col = n0 + wn * 32 + ni * 8 + ((l & 3) << 1);
                if (col < N) {
                    float v0 = acc[mi][ni][half * 2 + 0];
                    float v1 = acc[mi][ni][half * 2 + 1];
                    if (bias)  { v0 += bias[col]; v1 += bias[col + 1]; }
                    if (resid) { v0 += rp[col];   v1 += rp[col + 1]; }
                    *(float2*)(cp + col) = make_float2(v0, v1);
                }
            }
        }
    }
}

// ---------------- causal depthwise conv (K=4) + SiLU, plus softplus(dt) ----------
__global__ void conv_silu_kernel(const float* __restrict__ conv_w,
                                 const float* __restrict__ conv_b,
                                 const float* __restrict__ dt_bias)
{
    const int row = blockIdx.x;
    const int l = row & (L_SEQ - 1);
    for (int c = threadIdx.x; c < CONV_DIM; c += blockDim.x) {
        float accv = conv_b[c];
        #pragma unroll
        for (int k = 0; k < 4; k++) {
            int ls = l - 3 + k;
            if (ls >= 0) {
                size_t rr = (size_t)(row - 3 + k);
                accv += g_zx[rr * D_IN_PROJ + D_INNER + c] * conv_w[c * 4 + k];
            }
        }
        g_conv[(size_t)row * CONV_DIM + c] = accv / (1.f + expf(-accv));
    }
    if (threadIdx.x < NHEADS) {
        int h = threadIdx.x;
        float rawv = g_zx[(size_t)row * D_IN_PROJ + D_INNER + CONV_DIM + h] + dt_bias[h];
        float sp = (rawv > 20.f) ? rawv : log1pf(expf(rawv));
        g_dt[(size_t)row * NHEADS + h] = sp;
    }
}

// ======== chunked parallel scan: pass A (local from zero) ========================
__global__ void __launch_bounds__(256)
scanA_kernel(const float* __restrict__ A_log)
{
    const int c = blockIdx.x, h = blockIdx.y, b = blockIdx.z;
    const int tid = threadIdx.x;
    const int p = tid >> 2, q = tid & 3;
    const float Aneg = -expf(A_log[h]);

    __shared__ float sx[CS][64];
    __shared__ float sB[CS][16];
    __shared__ float sdt[CS];
    __shared__ float sdA[CS];

    const size_t rowbase = (size_t)b * L_SEQ + (size_t)c * CS;
    for (int idx = tid; idx < CS * 64; idx += 256) {
        int s = idx >> 6, pp = idx & 63;
        sx[s][pp] = g_conv[(rowbase + s) * CONV_DIM + h * 64 + pp];
    }
    for (int idx = tid; idx < CS * 16; idx += 256) {
        int s = idx >> 4, n = idx & 15;
        sB[s][n] = g_conv[(rowbase + s) * CONV_DIM + D_INNER + n];
    }
    if (tid < CS) {
        float dtv = g_dt[(rowbase + tid) * NHEADS + h];
        sdt[tid] = dtv;
        sdA[tid] = expf(dtv * Aneg);
    }
    __syncthreads();

    float h0 = 0.f, h1 = 0.f, h2 = 0.f, h3 = 0.f;
    #pragma unroll 4
    for (int s = 0; s < CS; s++) {
        float dA = sdA[s];
        float coef = sdt[s] * sx[s][p];
        float4 Bv = *(const float4*)&sB[s][q * 4];
        h0 = h0 * dA + coef * Bv.x;
        h1 = h1 * dA + coef * Bv.y;
        h2 = h2 * dA + coef * Bv.z;
        h3 = h3 * dA + coef * Bv.w;
    }
    size_t base = (((size_t)(b * NHEADS + h) * NC + c) << 10) + tid * 4;
    *(float4*)&g_hstate[base] = make_float4(h0, h1, h2, h3);
    if (tid == 0) {
        float P = 1.f;
        for (int s = 0; s < CS; s++) P *= sdA[s];
        g_P[(b * NHEADS + h) * NC + c] = P;
    }
}

// ======== chunked scan: middle combine (sequential over 64 chunks) ==============
__global__ void __launch_bounds__(256)
scanMid_kernel()
{
    const int h = blockIdx.x, b = blockIdx.y;
    const int tid = threadIdx.x;
    const size_t base = ((size_t)(b * NHEADS + h) * NC << 10) + tid * 4;
    const float* Pp = &g_P[(b * NHEADS + h) * NC];
    float4 run = make_float4(0.f, 0.f, 0.f, 0.f);
    for (int c = 0; c < NC; c++) {
        float4 endv = *(float4*)&g_hstate[base + ((size_t)c << 10)];
        float P = Pp[c];
        *(float4*)&g_hstate[base + ((size_t)c << 10)] = run;
        run.x = P * run.x + endv.x;
        run.y = P * run.y + endv.y;
        run.z = P * run.z + endv.z;
        run.w = P * run.w + endv.w;
    }
}

// ======== chunked scan: pass B (seeded, emit y) =================================
__global__ void __launch_bounds__(256)
scanB_kernel(const float* __restrict__ A_log, const float* __restrict__ Dp)
{
    const int c = blockIdx.x, h = blockIdx.y, b = blockIdx.z;
    const int tid = threadIdx.x;
    const int p = tid >> 2, q = tid & 3;
    const float Aneg = -expf(A_log[h]);
    const float Dh = Dp[h];

    __shared__ float sx[CS][64];
    __shared__ float sB[CS][16];
    __shared__ float sC[CS][16];
    __shared__ float sdt[CS];
    __shared__ float sdA[CS];
    __shared__ float sy[CS][64];

    const size_t rowbase = (size_t)b * L_SEQ + (size_t)c * CS;
    for (int idx = tid; idx < CS * 64; idx += 256) {
        int s = idx >> 6, pp = idx & 63;
        sx[s][pp] = g_conv[(rowbase + s) * CONV_DIM + h * 64 + pp];
    }
    for (int idx = tid; idx < CS * 16; idx += 256) {
        int s = idx >> 4, n = idx & 15;
        size_t rb = (rowbase + s) * CONV_DIM + D_INNER;
        sB[s][n] = g_conv[rb + n];
        sC[s][n] = g_conv[rb + D_STATE + n];
    }
    if (tid < CS) {
        float dtv = g_dt[(rowbase + tid) * NHEADS + h];
        sdt[tid] = dtv;
        sdA[tid] = expf(dtv * Aneg);
    }
    float4 hin = *(float4*)&g_hstate[(((size_t)(b * NHEADS + h) * NC + c) << 10) + tid * 4];
    __syncthreads();

    float h0 = hin.x, h1 = hin.y, h2 = hin.z, h3 = hin.w;
    for (int s = 0; s < CS; s++) {
        float dA = sdA[s];
        float xv = sx[s][p];
        float coef = sdt[s] * xv;
        float4 Bv = *(const float4*)&sB[s][q * 4];
        float4 Cv = *(const float4*)&sC[s][q * 4];
        h0 = h0 * dA + coef * Bv.x;
        h1 = h1 * dA + coef * Bv.y;
        h2 = h2 * dA + coef * Bv.z;
        h3 = h3 * dA + coef * Bv.w;
        float yp = h0 * Cv.x + h1 * Cv.y + h2 * Cv.z + h3 * Cv.w;
        yp += __shfl_xor_sync(0xffffffffu, yp, 1);
        yp += __shfl_xor_sync(0xffffffffu, yp, 2);
        if (q == 0) sy[s][p] = yp + Dh * xv;
    }
    __syncthreads();
    for (int idx = tid; idx < CS * 64; idx += 256) {
        int s = idx >> 6, pp = idx & 63;
        g_y[(rowbase + s) * D_INNER + h * 64 + pp] = sy[s][pp];
    }
}

// ---------------- y *= silu(z); RMSNorm(y) * norm_w  (in place) ------------------
__global__ void gate_rms_kernel(const float* __restrict__ norm_w)
{
    const int row = blockIdx.x, tid = threadIdx.x;
    const size_t yb = (size_t)row * D_INNER;
    const size_t zb = (size_t)row * D_IN_PROJ;
    float v[4];
    float ss = 0.f;
    #pragma unroll
    for (int j = 0; j < 4; j++) {
        int c = j * 256 + tid;
        float yv = g_y[yb + c];
        float z = g_zx[zb + c];
        yv *= z / (1.f + expf(-z));
        v[j] = yv;
        ss += yv * yv;
    }
    __shared__ float red[8];
    #pragma unroll
    for (int o = 16; o > 0; o >>= 1) ss += __shfl_xor_sync(0xffffffffu, ss, o);
    if ((tid & 31) == 0) red[tid >> 5] = ss;
    __syncthreads();
    float tot = red[0] + red[1] + red[2] + red[3] + red[4] + red[5] + red[6] + red[7];
    float sc = rsqrtf(tot * (1.f / D_INNER) + 1e-5f);
    #pragma unroll
    for (int j = 0; j < 4; j++) {
        int c = j * 256 + tid;
        g_y[yb + c] = v[j] * sc * norm_w[c];
    }
}

// ---------------- final LayerNorm over 512 -> d_out ------------------------------
__global__ void ln_kernel(const float* __restrict__ ln_w, const float* __restrict__ ln_b,
                          float* __restrict__ out)
{
    const int row = blockIdx.x, tid = threadIdx.x;  // 128 threads
    const size_t base = (size_t)row * D_MODEL;
    float v[4];
    float s = 0.f, s2 = 0.f;
    #pragma unroll
    for (int j = 0; j < 4; j++) {
        int c = j * 128 + tid;
        float xv = g_pre[base + c];
        v[j] = xv;
        s += xv;
        s2 += xv * xv;
    }
    __shared__ float rs[4], rs2[4];
    #pragma unroll
    for (int o = 16; o > 0; o >>= 1) {
        s  += __shfl_xor_sync(0xffffffffu, s, o);
        s2 += __shfl_xor_sync(0xffffffffu, s2, o);
    }
    if ((tid & 31) == 0) { rs[tid >> 5] = s; rs2[tid >> 5] = s2; }
    __syncthreads();
    float ts = rs[0] + rs[1] + rs[2] + rs[3];
    float ts2 = rs2[0] + rs2[1] + rs2[2] + rs2[3];
    float mu = ts * (1.f / D_MODEL);
    float var = ts2 * (1.f / D_MODEL) - mu * mu;
    float isd = rsqrtf(var + 1e-5f);
    #pragma unroll
    for (int j = 0; j < 4; j++) {
        int c = j * 128 + tid;
        out[base + c] = (v[j] - mu) * isd * ln_w[c] + ln_b[c];
    }
}

// ---------------- orchestration ---------------------------------------------------
extern "C" void kernel_launch(void* const* d_in, const int* in_sizes, int n_in,
                              void* d_out, int out_size)
{
    const float* x      = (const float*)d_in[0];
    const float* proj_w = (const float*)d_in[17];
    const float* proj_b = (const float*)d_in[18];
    const float* ln_w   = (const float*)d_in[19];
    const float* ln_b   = (const float*)d_in[20];

    float *zx, *yb, *dirout, *pre;
    cudaGetSymbolAddress((void**)&zx, g_zx);
    cudaGetSymbolAddress((void**)&yb, g_y);
    cudaGetSymbolAddress((void**)&dirout, g_dirout);
    cudaGetSymbolAddress((void**)&pre, g_pre);

    cudaFuncSetAttribute(gemm_tf32, cudaFuncAttributeMaxDynamicSharedMemorySize, GT_SMEM);

    for (int dir = 0; dir < 2; dir++) {
        const float* in_proj  = (const float*)d_in[1 + 8 * dir + 0];
        const float* conv_w   = (const float*)d_in[1 + 8 * dir + 1];
        const float* conv_b   = (const float*)d_in[1 + 8 * dir + 2];
        const float* dt_bias  = (const float*)d_in[1 + 8 * dir + 3];
        const float* A_log    = (const float*)d_in[1 + 8 * dir + 4];
        const float* Dp       = (const float*)d_in[1 + 8 * dir + 5];
        const float* norm_w   = (const float*)d_in[1 + 8 * dir + 6];
        const float* out_proj = (const float*)d_in[1 + 8 * dir + 7];

        gemm_tf32<<<dim3((D_IN_PROJ + 127) / 128, BL / 128), 256, GT_SMEM>>>(
            x, D_MODEL, in_proj, zx, D_IN_PROJ, 0,
            D_IN_PROJ, D_MODEL, dir, 0, nullptr, nullptr);

        conv_silu_kernel<<<BL, 256>>>(conv_w, conv_b, dt_bias);

        scanA_kernel<<<dim3(NC, NHEADS, B_SZ), 256>>>(A_log);
        scanMid_kernel<<<dim3(NHEADS, B_SZ), 256>>>();
        scanB_kernel<<<dim3(NC, NHEADS, B_SZ), 256>>>(A_log, Dp);

        gate_rms_kernel<<<BL, 256>>>(norm_w);

        gemm_tf32<<<dim3(D_MODEL / 128, BL / 128), 256, GT_SMEM>>>(
            yb, D_INNER, out_proj, dirout, D_INNER, dir * D_MODEL,
            D_MODEL, D_INNER, 0, dir, nullptr, nullptr);
    }

    gemm_tf32<<<dim3(D_MODEL / 128, BL / 128), 256, GT_SMEM>>>(
        dirout, D_INNER, proj_w, pre, D_MODEL, 0,
        D_MODEL, D_INNER, 0, 0, proj_b, x);

    ln_kernel<<<BL, 128>>>(ln_w, ln_b, (float*)d_out);
}

// round 6
// speedup vs baseline: 3.1297x; 1.0696x over previous
#include <cuda_runtime.h>
#include <cstdint>

#define B_SZ    8
#define L_SEQ   4096
#define D_MODEL 512
#define D_INNER 1024
#define NHEADS  16
#define HEADDIM 64
#define D_STATE 16
#define CONV_DIM 1056
#define D_IN_PROJ 2096
#define BL      (B_SZ * L_SEQ)
#define CS      64
#define NC      (L_SEQ / CS)

// ---------------- scratch (device globals; no allocation allowed) ----------------
__device__ float g_zx[2][(size_t)BL * D_IN_PROJ];
__device__ float g_conv[2][(size_t)BL * CONV_DIM];
__device__ float g_dt[2][(size_t)BL * NHEADS];
__device__ float g_y[2][(size_t)BL * D_INNER];
__device__ float g_dirout[(size_t)BL * D_INNER];
__device__ float g_pre[(size_t)BL * D_MODEL];
__device__ float g_hstate[2][(size_t)B_SZ * NHEADS * NC * 1024];
__device__ float g_P[2][B_SZ * NHEADS * NC];

__device__ __forceinline__ int fliprow(int r) {
    return (r & ~(L_SEQ - 1)) | ((L_SEQ - 1) - (r & (L_SEQ - 1)));
}
__device__ __forceinline__ void cpa16(uint32_t dst, const void* src, int sz) {
    asm volatile("cp.async.cg.shared.global [%0], [%1], 16, %2;"
                 :: "r"(dst), "l"(src), "r"(sz));
}
#define CP_COMMIT() asm volatile("cp.async.commit_group;" ::: "memory")
#define CP_WAIT1()  asm volatile("cp.async.wait_group 1;" ::: "memory")

// ============ tf32 mma.sync GEMM: C = A[M,K] @ W[N,K]^T (+bias +resid) ==========
// CTA tile 256x128, BK=32, 3-stage cp.async pipeline, 8 warps (4m x 2n),
// warp tile 64x64, mma m16n8k8.tf32. grid.z selects direction (A/W/C set, flips).
#define GT_STAGES 3
#define GT_ASZ 32768            /* 256 rows * 128B */
#define GT_BSZ 16384            /* 128 rows * 128B */
#define GT_STG (GT_ASZ + GT_BSZ)
#define GT_SMEM (GT_STAGES * GT_STG + 1024)

__global__ void __launch_bounds__(256, 1)
gemm_tf32(const float* __restrict__ A0, const float* __restrict__ A1, int lda,
          const float* __restrict__ W0, const float* __restrict__ W1,
          float* __restrict__ C0, float* __restrict__ C1, int ldc, int ccolstep,
          int N, int K, int flipAmask, int flipCmask,
          const float* __restrict__ bias,
          const float* __restrict__ resid)
{
    extern __shared__ char dsm[];
    const uint32_t sb_raw = (uint32_t)__cvta_generic_to_shared(dsm);
    const uint32_t sb = (sb_raw + 1023u) & ~1023u;

    const int z = blockIdx.z;
    const float* A = z ? A1 : A0;
    const float* W = z ? W1 : W0;
    float* C = z ? C1 : C0;
    const int ccol = z * ccolstep;
    const int flipA = (flipAmask >> z) & 1;
    const int flipC = (flipCmask >> z) & 1;

    const int tid = threadIdx.x;
    const int l   = tid & 31;
    const int w   = tid >> 5;
    const int wm  = w >> 1;                 // 0..3
    const int wn  = w & 1;                  // 0..1
    const int m0  = blockIdx.y * 256;
    const int n0  = blockIdx.x * 128;

    // ldmatrix fragment address precompute
    int aRB[4], aRX[4];
    const int ahc = (l >> 4) & 1;
    #pragma unroll
    for (int mi = 0; mi < 4; mi++) {
        int ar = wm * 64 + mi * 16 + ((l >> 3) & 1) * 8 + (l & 7);
        aRB[mi] = ar * 128;
        aRX[mi] = ar & 7;
    }
    int bRB[4], bRX[4];
    const int bkc = (l >> 3) & 1;
    #pragma unroll
    for (int p = 0; p < 4; p++) {
        int br = wn * 64 + p * 16 + ((l >> 4) & 1) * 8 + (l & 7);
        bRB[p] = br * 128;
        bRX[p] = br & 7;
    }

    // cp.async stage indices: A 8 x 16B, B 4 x 16B per thread
    int aswo[8], asch[8], arow[8];
    #pragma unroll
    for (int i = 0; i < 8; i++) {
        int q = tid + i * 256;
        int rr = q >> 3, ch = q & 7;
        asch[i] = ch;
        aswo[i] = rr * 128 + ((ch ^ (rr & 7)) << 4);
        int r = m0 + rr;
        arow[i] = flipA ? fliprow(r) : r;
    }
    int bswo[4], bsch[4], wrow[4], wvalid[4];
    #pragma unroll
    for (int i = 0; i < 4; i++) {
        int q = tid + i * 256;
        int rr = q >> 3, ch = q & 7;
        bsch[i] = ch;
        bswo[i] = rr * 128 + ((ch ^ (rr & 7)) << 4);
        int n = n0 + rr;
        wvalid[i] = (n < N) ? 16 : 0;
        wrow[i] = (n < N) ? n : 0;
    }

    float acc[4][8][4];
    #pragma unroll
    for (int mi = 0; mi < 4; mi++)
        #pragma unroll
        for (int ni = 0; ni < 8; ni++)
            #pragma unroll
            for (int k = 0; k < 4; k++) acc[mi][ni][k] = 0.f;

    auto issue = [&](int s) {
        const int k0 = s * 32;
        const uint32_t base = sb + (s % GT_STAGES) * GT_STG;
        #pragma unroll
        for (int i = 0; i < 8; i++)
            cpa16(base + aswo[i], A + (size_t)arow[i] * lda + k0 + asch[i] * 4, 16);
        #pragma unroll
        for (int i = 0; i < 4; i++)
            cpa16(base + GT_ASZ + bswo[i],
                  W + (size_t)wrow[i] * K + k0 + bsch[i] * 4, wvalid[i]);
    };
    auto compute = [&](int s) {
        const uint32_t Ab = sb + s * GT_STG;
        const uint32_t Bb = Ab + GT_ASZ;
        #pragma unroll
        for (int ks = 0; ks < 4; ks++) {
            uint32_t af[4][4];
            #pragma unroll
            for (int mi = 0; mi < 4; mi++) {
                uint32_t ad = Ab + aRB[mi] + ((((ks << 1) + ahc) ^ aRX[mi]) << 4);
                asm volatile("ldmatrix.sync.aligned.m8n8.x4.shared.b16 {%0,%1,%2,%3}, [%4];"
                    : "=r"(af[mi][0]), "=r"(af[mi][1]), "=r"(af[mi][2]), "=r"(af[mi][3])
                    : "r"(ad));
            }
            uint32_t bf[8][2];
            #pragma unroll
            for (int p = 0; p < 4; p++) {
                uint32_t bd = Bb + bRB[p] + ((((ks << 1) + bkc) ^ bRX[p]) << 4);
                uint32_t q0, q1, q2, q3;
                asm volatile("ldmatrix.sync.aligned.m8n8.x4.shared.b16 {%0,%1,%2,%3}, [%4];"
                    : "=r"(q0), "=r"(q1), "=r"(q2), "=r"(q3) : "r"(bd));
                bf[2 * p][0] = q0; bf[2 * p][1] = q1;
                bf[2 * p + 1][0] = q2; bf[2 * p + 1][1] = q3;
            }
            #pragma unroll
            for (int mi = 0; mi < 4; mi++)
                #pragma unroll
                for (int ni = 0; ni < 8; ni++) {
                    asm volatile(
                        "mma.sync.aligned.m16n8k8.row.col.f32.tf32.tf32.f32 "
                        "{%0,%1,%2,%3},{%4,%5,%6,%7},{%8,%9},{%0,%1,%2,%3};"
                        : "+f"(acc[mi][ni][0]), "+f"(acc[mi][ni][1]),
                          "+f"(acc[mi][ni][2]), "+f"(acc[mi][ni][3])
                        : "r"(af[mi][0]), "r"(af[mi][1]), "r"(af[mi][2]), "r"(af[mi][3]),
                          "r"(bf[ni][0]), "r"(bf[ni][1]));
                }
        }
    };

    const int KT = K / 32;
    issue(0); CP_COMMIT();
    issue(1); CP_COMMIT();
    for (int kt = 0; kt < KT; kt++) {
        CP_WAIT1();
        __syncthreads();
        if (kt + 2 < KT) issue(kt + 2);
        CP_COMMIT();
        compute(kt % GT_STAGES);
    }

    // epilogue
    #pragma unroll
    for (int mi = 0; mi < 4; mi++) {
        #pragma unroll
        for (int half = 0; half < 2; half++) {
            int r = m0 + wm * 64 + mi * 16 + (l >> 2) + half * 8;
            int cr = flipC ? fliprow(r) : r;
            float* cp = C + (size_t)cr * ldc + ccol;
            const float* rp = resid + (size_t)cr * ldc + ccol;
            #pragma unroll
            for (int ni = 0; ni < 8; ni++) {
                int col = n0 + wn * 64 + ni * 8 + ((l & 3) << 1);
                if (col < N) {
                    float v0 = acc[mi][ni][half * 2 + 0];
                    float v1 = acc[mi][ni][half * 2 + 1];
                    if (bias)  { v0 += bias[col]; v1 += bias[col + 1]; }
                    if (resid) { v0 += rp[col];   v1 += rp[col + 1]; }
                    *(float2*)(cp + col) = make_float2(v0, v1);
                }
            }
        }
    }
}

// ---------------- causal depthwise conv (K=4) + SiLU, plus softplus(dt) ----------
__global__ void conv_silu_kernel(const float* __restrict__ cw0, const float* __restrict__ cw1,
                                 const float* __restrict__ cb0, const float* __restrict__ cb1,
                                 const float* __restrict__ db0, const float* __restrict__ db1)
{
    const int row = blockIdx.x;
    const int dir = blockIdx.y;
    const float* conv_w  = dir ? cw1 : cw0;
    const float* conv_b  = dir ? cb1 : cb0;
    const float* dt_bias = dir ? db1 : db0;
    const float* zx = g_zx[dir];
    float* cv = g_conv[dir];
    const int l = row & (L_SEQ - 1);
    for (int c = threadIdx.x; c < CONV_DIM; c += blockDim.x) {
        float accv = conv_b[c];
        #pragma unroll
        for (int k = 0; k < 4; k++) {
            int ls = l - 3 + k;
            if (ls >= 0)
                accv += zx[(size_t)(row - 3 + k) * D_IN_PROJ + D_INNER + c] * conv_w[c * 4 + k];
        }
        cv[(size_t)row * CONV_DIM + c] = accv / (1.f + expf(-accv));
    }
    if (threadIdx.x < NHEADS) {
        int h = threadIdx.x;
        float rawv = zx[(size_t)row * D_IN_PROJ + D_INNER + CONV_DIM + h] + dt_bias[h];
        float sp = (rawv > 20.f) ? rawv : log1pf(expf(rawv));
        g_dt[dir][(size_t)row * NHEADS + h] = sp;
    }
}

// ======== chunked parallel scan: pass A (local from zero) ========================
__global__ void __launch_bounds__(256)
scanA_kernel(const float* __restrict__ Al0, const float* __restrict__ Al1)
{
    const int c = blockIdx.x, h = blockIdx.y;
    const int b = blockIdx.z & (B_SZ - 1), dir = blockIdx.z >> 3;
    const int tid = threadIdx.x;
    const int p = tid >> 2, q = tid & 3;
    const float Aneg = -expf((dir ? Al1 : Al0)[h]);
    const float* cv = g_conv[dir];

    __shared__ float sx[CS][64];
    __shared__ float sB[CS][16];
    __shared__ float sdt[CS];
    __shared__ float sdA[CS];

    const size_t rowbase = (size_t)b * L_SEQ + (size_t)c * CS;
    for (int idx = tid; idx < CS * 64; idx += 256) {
        int s = idx >> 6, pp = idx & 63;
        sx[s][pp] = cv[(rowbase + s) * CONV_DIM + h * 64 + pp];
    }
    for (int idx = tid; idx < CS * 16; idx += 256) {
        int s = idx >> 4, n = idx & 15;
        sB[s][n] = cv[(rowbase + s) * CONV_DIM + D_INNER + n];
    }
    if (tid < CS) {
        float dtv = g_dt[dir][(rowbase + tid) * NHEADS + h];
        sdt[tid] = dtv;
        sdA[tid] = expf(dtv * Aneg);
    }
    __syncthreads();

    float h0 = 0.f, h1 = 0.f, h2 = 0.f, h3 = 0.f;
    #pragma unroll 4
    for (int s = 0; s < CS; s++) {
        float dA = sdA[s];
        float coef = sdt[s] * sx[s][p];
        float4 Bv = *(const float4*)&sB[s][q * 4];
        h0 = h0 * dA + coef * Bv.x;
        h1 = h1 * dA + coef * Bv.y;
        h2 = h2 * dA + coef * Bv.z;
        h3 = h3 * dA + coef * Bv.w;
    }
    size_t base = (((size_t)(b * NHEADS + h) * NC + c) << 10) + tid * 4;
    *(float4*)&g_hstate[dir][base] = make_float4(h0, h1, h2, h3);
    if (tid == 0) {
        float P = 1.f;
        for (int s = 0; s < CS; s++) P *= sdA[s];
        g_P[dir][(b * NHEADS + h) * NC + c] = P;
    }
}

// ======== chunked scan: middle combine (sequential over 64 chunks, prefetched) ==
__global__ void __launch_bounds__(256)
scanMid_kernel()
{
    const int h = blockIdx.x, b = blockIdx.y, dir = blockIdx.z;
    const int tid = threadIdx.x;
    float* hs = g_hstate[dir];
    const size_t base = ((size_t)(b * NHEADS + h) * NC << 10) + tid * 4;
    __shared__ float sP[NC];
    if (tid < NC) sP[tid] = g_P[dir][(b * NHEADS + h) * NC + tid];
    __syncthreads();
    float4 nxt = *(float4*)&hs[base];
    float4 run = make_float4(0.f, 0.f, 0.f, 0.f);
    for (int c = 0; c < NC; c++) {
        float4 endv = nxt;
        if (c + 1 < NC) nxt = *(float4*)&hs[base + ((size_t)(c + 1) << 10)];
        *(float4*)&hs[base + ((size_t)c << 10)] = run;
        float P = sP[c];
        run.x = P * run.x + endv.x;
        run.y = P * run.y + endv.y;
        run.z = P * run.z + endv.z;
        run.w = P * run.w + endv.w;
    }
}

// ======== chunked scan: pass B (seeded, emit y) =================================
__global__ void __launch_bounds__(256)
scanB_kernel(const float* __restrict__ Al0, const float* __restrict__ Al1,
             const float* __restrict__ Dp0, const float* __restrict__ Dp1)
{
    const int c = blockIdx.x, h = blockIdx.y;
    const int b = blockIdx.z & (B_SZ - 1), dir = blockIdx.z >> 3;
    const int tid = threadIdx.x;
    const int p = tid >> 2, q = tid & 3;
    const float Aneg = -expf((dir ? Al1 : Al0)[h]);
    const float Dh = (dir ? Dp1 : Dp0)[h];
    const float* cv = g_conv[dir];

    __shared__ float sx[CS][64];
    __shared__ float sB[CS][16];
    __shared__ float sC[CS][16];
    __shared__ float sdt[CS];
    __shared__ float sdA[CS];
    __shared__ float sy[CS][64];

    const size_t rowbase = (size_t)b * L_SEQ + (size_t)c * CS;
    for (int idx = tid; idx < CS * 64; idx += 256) {
        int s = idx >> 6, pp = idx & 63;
        sx[s][pp] = cv[(rowbase + s) * CONV_DIM + h * 64 + pp];
    }
    for (int idx = tid; idx < CS * 16; idx += 256) {
        int s = idx >> 4, n = idx & 15;
        size_t rb = (rowbase + s) * CONV_DIM + D_INNER;
        sB[s][n] = cv[rb + n];
        sC[s][n] = cv[rb + D_STATE + n];
    }
    if (tid < CS) {
        float dtv = g_dt[dir][(rowbase + tid) * NHEADS + h];
        sdt[tid] = dtv;
        sdA[tid] = expf(dtv * Aneg);
    }
    float4 hin = *(float4*)&g_hstate[dir][(((size_t)(b * NHEADS + h) * NC + c) << 10) + tid * 4];
    __syncthreads();

    float h0 = hin.x, h1 = hin.y, h2 = hin.z, h3 = hin.w;
    for (int s = 0; s < CS; s++) {
        float dA = sdA[s];
        float xv = sx[s][p];
        float coef = sdt[s] * xv;
        float4 Bv = *(const float4*)&sB[s][q * 4];
        float4 Cv = *(const float4*)&sC[s][q * 4];
        h0 = h0 * dA + coef * Bv.x;
        h1 = h1 * dA + coef * Bv.y;
        h2 = h2 * dA + coef * Bv.z;
        h3 = h3 * dA + coef * Bv.w;
        float yp = h0 * Cv.x + h1 * Cv.y + h2 * Cv.z + h3 * Cv.w;
        yp += __shfl_xor_sync(0xffffffffu, yp, 1);
        yp += __shfl_xor_sync(0xffffffffu, yp, 2);
        if (q == 0) sy[s][p] = yp + Dh * xv;
    }
    __syncthreads();
    for (int idx = tid; idx < CS * 64; idx += 256) {
        int s = idx >> 6, pp = idx & 63;
        g_y[dir][(rowbase + s) * D_INNER + h * 64 + pp] = sy[s][pp];
    }
}

// ---------------- y *= silu(z); RMSNorm(y) * norm_w  (in place, float4) ----------
__global__ void gate_rms_kernel(const float* __restrict__ nw0, const float* __restrict__ nw1)
{
    const int row = blockIdx.x, dir = blockIdx.y, tid = threadIdx.x;
    const float* norm_w = dir ? nw1 : nw0;
    float* yv4p = &g_y[dir][(size_t)row * D_INNER + tid * 4];
    const float* zp = &g_zx[dir][(size_t)row * D_IN_PROJ + tid * 4];
    float4 yv = *(float4*)yv4p;
    float4 zv = *(const float4*)zp;
    yv.x *= zv.x / (1.f + expf(-zv.x));
    yv.y *= zv.y / (1.f + expf(-zv.y));
    yv.z *= zv.z / (1.f + expf(-zv.z));
    yv.w *= zv.w / (1.f + expf(-zv.w));
    float ss = yv.x * yv.x + yv.y * yv.y + yv.z * yv.z + yv.w * yv.w;
    __shared__ float red[8];
    #pragma unroll
    for (int o = 16; o > 0; o >>= 1) ss += __shfl_xor_sync(0xffffffffu, ss, o);
    if ((tid & 31) == 0) red[tid >> 5] = ss;
    __syncthreads();
    float tot = red[0] + red[1] + red[2] + red[3] + red[4] + red[5] + red[6] + red[7];
    float sc = rsqrtf(tot * (1.f / D_INNER) + 1e-5f);
    float4 nv = *(const float4*)&norm_w[tid * 4];
    yv.x *= sc * nv.x; yv.y *= sc * nv.y; yv.z *= sc * nv.z; yv.w *= sc * nv.w;
    *(float4*)yv4p = yv;
}

// ---------------- final LayerNorm over 512 -> d_out ------------------------------
__global__ void ln_kernel(const float* __restrict__ ln_w, const float* __restrict__ ln_b,
                          float* __restrict__ out)
{
    const int row = blockIdx.x, tid = threadIdx.x;  // 128 threads
    const size_t base = (size_t)row * D_MODEL;
    float4 v = *(const float4*)&g_pre[base + tid * 4];
    float s = v.x + v.y + v.z + v.w;
    float s2 = v.x * v.x + v.y * v.y + v.z * v.z + v.w * v.w;
    __shared__ float rs[4], rs2[4];
    #pragma unroll
    for (int o = 16; o > 0; o >>= 1) {
        s  += __shfl_xor_sync(0xffffffffu, s, o);
        s2 += __shfl_xor_sync(0xffffffffu, s2, o);
    }
    if ((tid & 31) == 0) { rs[tid >> 5] = s; rs2[tid >> 5] = s2; }
    __syncthreads();
    float ts = rs[0] + rs[1] + rs[2] + rs[3];
    float ts2 = rs2[0] + rs2[1] + rs2[2] + rs2[3];
    float mu = ts * (1.f / D_MODEL);
    float var = ts2 * (1.f / D_MODEL) - mu * mu;
    float isd = rsqrtf(var + 1e-5f);
    float4 wv = *(const float4*)&ln_w[tid * 4];
    float4 bv = *(const float4*)&ln_b[tid * 4];
    float4 o;
    o.x = (v.x - mu) * isd * wv.x + bv.x;
    o.y = (v.y - mu) * isd * wv.y + bv.y;
    o.z = (v.z - mu) * isd * wv.z + bv.z;
    o.w = (v.w - mu) * isd * wv.w + bv.w;
    *(float4*)&out[base + tid * 4] = o;
}

// ---------------- orchestration ---------------------------------------------------
extern "C" void kernel_launch(void* const* d_in, const int* in_sizes, int n_in,
                              void* d_out, int out_size)
{
    const float* x      = (const float*)d_in[0];
    const float* f_in_proj  = (const float*)d_in[1];
    const float* f_conv_w   = (const float*)d_in[2];
    const float* f_conv_b   = (const float*)d_in[3];
    const float* f_dt_bias  = (const float*)d_in[4];
    const float* f_A_log    = (const float*)d_in[5];
    const float* f_D        = (const float*)d_in[6];
    const float* f_norm_w   = (const float*)d_in[7];
    const float* f_out_proj = (const float*)d_in[8];
    const float* b_in_proj  = (const float*)d_in[9];
    const float* b_conv_w   = (const float*)d_in[10];
    const float* b_conv_b   = (const float*)d_in[11];
    const float* b_dt_bias  = (const float*)d_in[12];
    const float* b_A_log    = (const float*)d_in[13];
    const float* b_D        = (const float*)d_in[14];
    const float* b_norm_w   = (const float*)d_in[15];
    const float* b_out_proj = (const float*)d_in[16];
    const float* proj_w = (const float*)d_in[17];
    const float* proj_b = (const float*)d_in[18];
    const float* ln_w   = (const float*)d_in[19];
    const float* ln_b   = (const float*)d_in[20];

    float *zx0, *zx1, *y0, *y1, *dirout, *pre;
    cudaGetSymbolAddress((void**)&zx0, g_zx);
    zx1 = zx0 + (size_t)BL * D_IN_PROJ;
    cudaGetSymbolAddress((void**)&y0, g_y);
    y1 = y0 + (size_t)BL * D_INNER;
    cudaGetSymbolAddress((void**)&dirout, g_dirout);
    cudaGetSymbolAddress((void**)&pre, g_pre);

    cudaFuncSetAttribute(gemm_tf32, cudaFuncAttributeMaxDynamicSharedMemorySize, GT_SMEM);

    // in_proj both dirs: zx[z] = x(flip if z) @ in_proj[z]^T
    gemm_tf32<<<dim3((D_IN_PROJ + 127) / 128, BL / 256, 2), 256, GT_SMEM>>>(
        x, x, D_MODEL, f_in_proj, b_in_proj, zx0, zx1, D_IN_PROJ, 0,
        D_IN_PROJ, D_MODEL, 0b10, 0, nullptr, nullptr);

    conv_silu_kernel<<<dim3(BL, 2), 256>>>(f_conv_w, b_conv_w, f_conv_b, b_conv_b,
                                           f_dt_bias, b_dt_bias);

    scanA_kernel<<<dim3(NC, NHEADS, 2 * B_SZ), 256>>>(f_A_log, b_A_log);
    scanMid_kernel<<<dim3(NHEADS, B_SZ, 2), 256>>>();
    scanB_kernel<<<dim3(NC, NHEADS, 2 * B_SZ), 256>>>(f_A_log, b_A_log, f_D, b_D);

    gate_rms_kernel<<<dim3(BL, 2), 256>>>(f_norm_w, b_norm_w);

    // out_proj both dirs into g_dirout halves; bwd written time-flipped
    gemm_tf32<<<dim3(D_MODEL / 128, BL / 256, 2), 256, GT_SMEM>>>(
        y0, y1, D_INNER, f_out_proj, b_out_proj, dirout, dirout, D_INNER, D_MODEL,
        D_MODEL, D_INNER, 0, 0b10, nullptr, nullptr);

    // pre = x + proj_b + [fwd|bwd] @ proj_w^T
    gemm_tf32<<<dim3(D_MODEL / 128, BL / 256, 1), 256, GT_SMEM>>>(
        dirout, dirout, D_INNER, proj_w, proj_w, pre, pre, D_MODEL, 0,
        D_MODEL, D_INNER, 0, 0, proj_b, x);

    ln_kernel<<<BL, 128>>>(ln_w, ln_b, (float*)d_out);
}

// round 7
// speedup vs baseline: 3.5373x; 1.1303x over previous
#include <cuda_runtime.h>
#include <cuda_fp16.h>
#include <cstdint>

#define B_SZ    8
#define L_SEQ   4096
#define D_MODEL 512
#define D_INNER 1024
#define NHEADS  16
#define HEADDIM 64
#define D_STATE 16
#define CONV_DIM 1056
#define D_IN_PROJ 2096
#define BL      (B_SZ * L_SEQ)
#define CS      64
#define NC      (L_SEQ / CS)

// ---------------- scratch (device globals; no allocation allowed) ----------------
__device__ float g_zx[2][(size_t)BL * D_IN_PROJ];
__device__ float g_conv[2][(size_t)BL * CONV_DIM];
__device__ float g_dt[2][(size_t)BL * NHEADS];
__device__ float g_y[2][(size_t)BL * D_INNER];
__device__ float g_pre[(size_t)BL * D_MODEL];
__device__ float g_hstate[2][(size_t)B_SZ * NHEADS * NC * 1024];
__device__ float g_P[2][B_SZ * NHEADS * NC];

__device__ __half g_x16[(size_t)BL * D_MODEL];
__device__ __half g_wip16[2][(size_t)D_IN_PROJ * D_MODEL];
__device__ __half g_wop16[2][(size_t)D_MODEL * D_INNER];
__device__ __half g_wpr16[(size_t)D_MODEL * D_INNER];
__device__ __half g_y16[2][(size_t)BL * D_INNER];
__device__ __half g_do16[(size_t)BL * D_INNER];

__device__ __forceinline__ int fliprow(int r) {
    return (r & ~(L_SEQ - 1)) | ((L_SEQ - 1) - (r & (L_SEQ - 1)));
}
__device__ __forceinline__ void cpa16(uint32_t dst, const void* src, int sz) {
    asm volatile("cp.async.cg.shared.global [%0], [%1], 16, %2;"
                 :: "r"(dst), "l"(src), "r"(sz));
}
#define CP_COMMIT() asm volatile("cp.async.commit_group;" ::: "memory")
#define CP_WAIT1()  asm volatile("cp.async.wait_group 1;" ::: "memory")

// ---------------- fp32 -> fp16 convert (grid-stride, float4) ---------------------
__global__ void f2h_kernel(const float* __restrict__ src, __half* __restrict__ dst, int n4)
{
    for (int i = blockIdx.x * blockDim.x + threadIdx.x; i < n4; i += gridDim.x * blockDim.x) {
        float4 v = *(const float4*)(src + (size_t)i * 4);
        __half2* d = (__half2*)(dst + (size_t)i * 4);
        d[0] = __floats2half2_rn(v.x, v.y);
        d[1] = __floats2half2_rn(v.z, v.w);
    }
}

// ============ fp16 mma.sync GEMM: C = A[M,K] @ W[N,K]^T (+bias +resid) ==========
// CTA tile 256x128, BK=32, 3-stage cp.async, 8 warps (4m x 2n), warp tile 64x64,
// mma m16n8k16.f16 with fp32 accumulate. grid.z selects direction.
#define GT_STAGES 3
#define GT_ASZ 16384            /* 256 rows * 64B */
#define GT_BSZ 8192             /* 128 rows * 64B */
#define GT_STG (GT_ASZ + GT_BSZ)
#define GT_SMEM (GT_STAGES * GT_STG + 1024)

__global__ void __launch_bounds__(256, 1)
gemm_f16(const __half* __restrict__ A0, const __half* __restrict__ A1, int lda,
         const __half* __restrict__ W0, const __half* __restrict__ W1,
         void* C0v, void* C1v, int ldc, int ccolstep,
         int N, int K, int flipAmask, int flipCmask, int halfOut,
         const float* __restrict__ bias,
         const float* __restrict__ resid)
{
    extern __shared__ char dsm[];
    const uint32_t sb_raw = (uint32_t)__cvta_generic_to_shared(dsm);
    const uint32_t sb = (sb_raw + 1023u) & ~1023u;

    const int z = blockIdx.z;
    const __half* A = z ? A1 : A0;
    const __half* W = z ? W1 : W0;
    void* Cv = z ? C1v : C0v;
    const int ccol = z * ccolstep;
    const int flipA = (flipAmask >> z) & 1;
    const int flipC = (flipCmask >> z) & 1;

    const int tid = threadIdx.x;
    const int l   = tid & 31;
    const int w   = tid >> 5;
    const int wm  = w >> 1;                 // 0..3
    const int wn  = w & 1;                  // 0..1
    const int m0  = blockIdx.y * 256;
    const int n0  = blockIdx.x * 128;

    // ldmatrix lane row/swizzle precompute: row-in-fragment = l&15, chunk-half = l>>4
    const int lr = l & 15;
    const int lc = l >> 4;
    const int lx = lr & 3;                   // swizzle XOR bits

    // cp.async stage indices: A 4 x 16B, B 2 x 16B per thread
    int aswo[4], asch[4], arow[4];
    #pragma unroll
    for (int i = 0; i < 4; i++) {
        int q = tid + i * 256;
        int rr = q >> 2, ch = q & 3;
        asch[i] = ch;
        aswo[i] = rr * 64 + ((ch ^ (rr & 3)) << 4);
        int r = m0 + rr;
        arow[i] = flipA ? fliprow(r) : r;
    }
    int bswo[2], bsch[2], wrow[2], wvalid[2];
    #pragma unroll
    for (int i = 0; i < 2; i++) {
        int q = tid + i * 256;
        int rr = q >> 2, ch = q & 3;
        bsch[i] = ch;
        bswo[i] = rr * 64 + ((ch ^ (rr & 3)) << 4);
        int n = n0 + rr;
        wvalid[i] = (n < N) ? 16 : 0;
        wrow[i] = (n < N) ? n : 0;
    }

    float acc[4][8][4];
    #pragma unroll
    for (int mi = 0; mi < 4; mi++)
        #pragma unroll
        for (int ni = 0; ni < 8; ni++)
            #pragma unroll
            for (int k = 0; k < 4; k++) acc[mi][ni][k] = 0.f;

    auto issue = [&](int s) {
        const int k0 = s * 32;
        const uint32_t base = sb + (s % GT_STAGES) * GT_STG;
        #pragma unroll
        for (int i = 0; i < 4; i++)
            cpa16(base + aswo[i], A + (size_t)arow[i] * lda + k0 + asch[i] * 8, 16);
        #pragma unroll
        for (int i = 0; i < 2; i++)
            cpa16(base + GT_ASZ + bswo[i],
                  W + (size_t)wrow[i] * K + k0 + bsch[i] * 8, wvalid[i]);
    };
    auto compute = [&](int s) {
        const uint32_t Ab = sb + s * GT_STG;
        const uint32_t Bb = Ab + GT_ASZ;
        #pragma unroll
        for (int ks = 0; ks < 2; ks++) {
            const int chsel = ((ks << 1) | lc) ^ lx;
            uint32_t af[4][4];
            #pragma unroll
            for (int mi = 0; mi < 4; mi++) {
                uint32_t ad = Ab + (wm * 64 + mi * 16 + lr) * 64 + (chsel << 4);
                asm volatile("ldmatrix.sync.aligned.m8n8.x4.shared.b16 {%0,%1,%2,%3}, [%4];"
                    : "=r"(af[mi][0]), "=r"(af[mi][1]), "=r"(af[mi][2]), "=r"(af[mi][3])
                    : "r"(ad));
            }
            uint32_t bf[8][2];
            #pragma unroll
            for (int p = 0; p < 4; p++) {
                uint32_t bd = Bb + (wn * 64 + p * 16 + lr) * 64 + (chsel << 4);
                uint32_t q0, q1, q2, q3;
                asm volatile("ldmatrix.sync.aligned.m8n8.x4.shared.b16 {%0,%1,%2,%3}, [%4];"
                    : "=r"(q0), "=r"(q1), "=r"(q2), "=r"(q3) : "r"(bd));
                bf[2 * p][0] = q0;     bf[2 * p][1] = q2;
                bf[2 * p + 1][0] = q1; bf[2 * p + 1][1] = q3;
            }
            #pragma unroll
            for (int mi = 0; mi < 4; mi++)
                #pragma unroll
                for (int ni = 0; ni < 8; ni++) {
                    asm volatile(
                        "mma.sync.aligned.m16n8k16.row.col.f32.f16.f16.f32 "
                        "{%0,%1,%2,%3},{%4,%5,%6,%7},{%8,%9},{%0,%1,%2,%3};"
                        : "+f"(acc[mi][ni][0]), "+f"(acc[mi][ni][1]),
                          "+f"(acc[mi][ni][2]), "+f"(acc[mi][ni][3])
                        : "r"(af[mi][0]), "r"(af[mi][1]), "r"(af[mi][2]), "r"(af[mi][3]),
                          "r"(bf[ni][0]), "r"(bf[ni][1]));
                }
        }
    };

    const int KT = K / 32;
    issue(0); CP_COMMIT();
    issue(1); CP_COMMIT();
    for (int kt = 0; kt < KT; kt++) {
        CP_WAIT1();
        __syncthreads();
        if (kt + 2 < KT) issue(kt + 2);
        CP_COMMIT();
        compute(kt % GT_STAGES);
    }

    // epilogue
    #pragma unroll
    for (int mi = 0; mi < 4; mi++) {
        #pragma unroll
        for (int half = 0; half < 2; half++) {
            int r = m0 + wm * 64 + mi * 16 + (l >> 2) + half * 8;
            int cr = flipC ? fliprow(r) : r;
            const float* rp = resid + (size_t)cr * ldc + ccol;
            #pragma unroll
            for (int ni = 0; ni < 8; ni++) {
                int col = n0 + wn * 64 + ni * 8 + ((l & 3) << 1);
                if (col < N) {
                    float v0 = acc[mi][ni][half * 2 + 0];
                    float v1 = acc[mi][ni][half * 2 + 1];
                    if (bias)  { v0 += bias[col]; v1 += bias[col + 1]; }
                    if (resid) { v0 += rp[col];   v1 += rp[col + 1]; }
                    if (halfOut) {
                        __half2* hp = (__half2*)((__half*)Cv + (size_t)cr * ldc + ccol + col);
                        *hp = __floats2half2_rn(v0, v1);
                    } else {
                        float* cp = (float*)Cv + (size_t)cr * ldc + ccol;
                        *(float2*)(cp + col) = make_float2(v0, v1);
                    }
                }
            }
        }
    }
}

// ---------------- causal depthwise conv (K=4) + SiLU, plus softplus(dt) ----------
__global__ void conv_silu_kernel(const float* __restrict__ cw0, const float* __restrict__ cw1,
                                 const float* __restrict__ cb0, const float* __restrict__ cb1,
                                 const float* __restrict__ db0, const float* __restrict__ db1)
{
    const int row = blockIdx.x;
    const int dir = blockIdx.y;
    const float* conv_w  = dir ? cw1 : cw0;
    const float* conv_b  = dir ? cb1 : cb0;
    const float* dt_bias = dir ? db1 : db0;
    const float* zx = g_zx[dir];
    float* cv = g_conv[dir];
    const int l = row & (L_SEQ - 1);
    for (int c = threadIdx.x; c < CONV_DIM; c += blockDim.x) {
        float accv = conv_b[c];
        #pragma unroll
        for (int k = 0; k < 4; k++) {
            int ls = l - 3 + k;
            if (ls >= 0)
                accv += zx[(size_t)(row - 3 + k) * D_IN_PROJ + D_INNER + c] * conv_w[c * 4 + k];
        }
        cv[(size_t)row * CONV_DIM + c] = accv / (1.f + expf(-accv));
    }
    if (threadIdx.x < NHEADS) {
        int h = threadIdx.x;
        float rawv = zx[(size_t)row * D_IN_PROJ + D_INNER + CONV_DIM + h] + dt_bias[h];
        float sp = (rawv > 20.f) ? rawv : log1pf(expf(rawv));
        g_dt[dir][(size_t)row * NHEADS + h] = sp;
    }
}

// ======== chunked parallel scan: pass A (local from zero) ========================
__global__ void __launch_bounds__(256)
scanA_kernel(const float* __restrict__ Al0, const float* __restrict__ Al1)
{
    const int c = blockIdx.x, h = blockIdx.y;
    const int b = blockIdx.z & (B_SZ - 1), dir = blockIdx.z >> 3;
    const int tid = threadIdx.x;
    const int p = tid >> 2, q = tid & 3;
    const float Aneg = -expf((dir ? Al1 : Al0)[h]);
    const float* cv = g_conv[dir];

    __shared__ float sx[CS][64];
    __shared__ float sB[CS][16];
    __shared__ float sdt[CS];
    __shared__ float sdA[CS];

    const size_t rowbase = (size_t)b * L_SEQ + (size_t)c * CS;
    for (int idx = tid; idx < CS * 64; idx += 256) {
        int s = idx >> 6, pp = idx & 63;
        sx[s][pp] = cv[(rowbase + s) * CONV_DIM + h * 64 + pp];
    }
    for (int idx = tid; idx < CS * 16; idx += 256) {
        int s = idx >> 4, n = idx & 15;
        sB[s][n] = cv[(rowbase + s) * CONV_DIM + D_INNER + n];
    }
    if (tid < CS) {
        float dtv = g_dt[dir][(rowbase + tid) * NHEADS + h];
        sdt[tid] = dtv;
        sdA[tid] = expf(dtv * Aneg);
    }
    __syncthreads();

    float h0 = 0.f, h1 = 0.f, h2 = 0.f, h3 = 0.f;
    #pragma unroll 4
    for (int s = 0; s < CS; s++) {
        float dA = sdA[s];
        float coef = sdt[s] * sx[s][p];
        float4 Bv = *(const float4*)&sB[s][q * 4];
        h0 = h0 * dA + coef * Bv.x;
        h1 = h1 * dA + coef * Bv.y;
        h2 = h2 * dA + coef * Bv.z;
        h3 = h3 * dA + coef * Bv.w;
    }
    size_t base = (((size_t)(b * NHEADS + h) * NC + c) << 10) + tid * 4;
    *(float4*)&g_hstate[dir][base] = make_float4(h0, h1, h2, h3);
    if (tid == 0) {
        float P = 1.f;
        for (int s = 0; s < CS; s++) P *= sdA[s];
        g_P[dir][(b * NHEADS + h) * NC + c] = P;
    }
}

// ======== chunked scan: middle combine (sequential over 64 chunks, prefetched) ==
__global__ void __launch_bounds__(256)
scanMid_kernel()
{
    const int h = blockIdx.x, b = blockIdx.y, dir = blockIdx.z;
    const int tid = threadIdx.x;
    float* hs = g_hstate[dir];
    const size_t base = ((size_t)(b * NHEADS + h) * NC << 10) + tid * 4;
    __shared__ float sP[NC];
    if (tid < NC) sP[tid] = g_P[dir][(b * NHEADS + h) * NC + tid];
    __syncthreads();
    float4 nxt = *(float4*)&hs[base];
    float4 run = make_float4(0.f, 0.f, 0.f, 0.f);
    for (int c = 0; c < NC; c++) {
        float4 endv = nxt;
        if (c + 1 < NC) nxt = *(float4*)&hs[base + ((size_t)(c + 1) << 10)];
        *(float4*)&hs[base + ((size_t)c << 10)] = run;
        float P = sP[c];
        run.x = P * run.x + endv.x;
        run.y = P * run.y + endv.y;
        run.z = P * run.z + endv.z;
        run.w = P * run.w + endv.w;
    }
}

// ======== chunked scan: pass B (seeded, emit y) =================================
__global__ void __launch_bounds__(256)
scanB_kernel(const float* __restrict__ Al0, const float* __restrict__ Al1,
             const float* __restrict__ Dp0, const float* __restrict__ Dp1)
{
    const int c = blockIdx.x, h = blockIdx.y;
    const int b = blockIdx.z & (B_SZ - 1), dir = blockIdx.z >> 3;
    const int tid = threadIdx.x;
    const int p = tid >> 2, q = tid & 3;
    const float Aneg = -expf((dir ? Al1 : Al0)[h]);
    const float Dh = (dir ? Dp1 : Dp0)[h];
    const float* cv = g_conv[dir];

    __shared__ float sx[CS][64];
    __shared__ float sB[CS][16];
    __shared__ float sC[CS][16];
    __shared__ float sdt[CS];
    __shared__ float sdA[CS];
    __shared__ float sy[CS][64];

    const size_t rowbase = (size_t)b * L_SEQ + (size_t)c * CS;
    for (int idx = tid; idx < CS * 64; idx += 256) {
        int s = idx >> 6, pp = idx & 63;
        sx[s][pp] = cv[(rowbase + s) * CONV_DIM + h * 64 + pp];
    }
    for (int idx = tid; idx < CS * 16; idx += 256) {
        int s = idx >> 4, n = idx & 15;
        size_t rb = (rowbase + s) * CONV_DIM + D_INNER;
        sB[s][n] = cv[rb + n];
        sC[s][n] = cv[rb + D_STATE + n];
    }
    if (tid < CS) {
        float dtv = g_dt[dir][(rowbase + tid) * NHEADS + h];
        sdt[tid] = dtv;
        sdA[tid] = expf(dtv * Aneg);
    }
    float4 hin = *(float4*)&g_hstate[dir][(((size_t)(b * NHEADS + h) * NC + c) << 10) + tid * 4];
    __syncthreads();

    float h0 = hin.x, h1 = hin.y, h2 = hin.z, h3 = hin.w;
    for (int s = 0; s < CS; s++) {
        float dA = sdA[s];
        float xv = sx[s][p];
        float coef = sdt[s] * xv;
        float4 Bv = *(const float4*)&sB[s][q * 4];
        float4 Cv = *(const float4*)&sC[s][q * 4];
        h0 = h0 * dA + coef * Bv.x;
        h1 = h1 * dA + coef * Bv.y;
        h2 = h2 * dA + coef * Bv.z;
        h3 = h3 * dA + coef * Bv.w;
        float yp = h0 * Cv.x + h1 * Cv.y + h2 * Cv.z + h3 * Cv.w;
        yp += __shfl_xor_sync(0xffffffffu, yp, 1);
        yp += __shfl_xor_sync(0xffffffffu, yp, 2);
        if (q == 0) sy[s][p] = yp + Dh * xv;
    }
    __syncthreads();
    for (int idx = tid; idx < CS * 64; idx += 256) {
        int s = idx >> 6, pp = idx & 63;
        g_y[dir][(rowbase + s) * D_INNER + h * 64 + pp] = sy[s][pp];
    }
}

// ------- y *= silu(z); RMSNorm(y) * norm_w; emit fp16 for out_proj GEMM ----------
__global__ void gate_rms_kernel(const float* __restrict__ nw0, const float* __restrict__ nw1)
{
    const int row = blockIdx.x, dir = blockIdx.y, tid = threadIdx.x;
    const float* norm_w = dir ? nw1 : nw0;
    const float* yp = &g_y[dir][(size_t)row * D_INNER + tid * 4];
    const float* zp = &g_zx[dir][(size_t)row * D_IN_PROJ + tid * 4];
    float4 yv = *(const float4*)yp;
    float4 zv = *(const float4*)zp;
    yv.x *= zv.x / (1.f + expf(-zv.x));
    yv.y *= zv.y / (1.f + expf(-zv.y));
    yv.z *= zv.z / (1.f + expf(-zv.z));
    yv.w *= zv.w / (1.f + expf(-zv.w));
    float ss = yv.x * yv.x + yv.y * yv.y + yv.z * yv.z + yv.w * yv.w;
    __shared__ float red[8];
    #pragma unroll
    for (int o = 16; o > 0; o >>= 1) ss += __shfl_xor_sync(0xffffffffu, ss, o);
    if ((tid & 31) == 0) red[tid >> 5] = ss;
    __syncthreads();
    float tot = red[0] + red[1] + red[2] + red[3] + red[4] + red[5] + red[6] + red[7];
    float sc = rsqrtf(tot * (1.f / D_INNER) + 1e-5f);
    float4 nv = *(const float4*)&norm_w[tid * 4];
    __half2* hp = (__half2*)&g_y16[dir][(size_t)row * D_INNER + tid * 4];
    hp[0] = __floats2half2_rn(yv.x * sc * nv.x, yv.y * sc * nv.y);
    hp[1] = __floats2half2_rn(yv.z * sc * nv.z, yv.w * sc * nv.w);
}

// ---------------- final LayerNorm over 512 -> d_out ------------------------------
__global__ void ln_kernel(const float* __restrict__ ln_w, const float* __restrict__ ln_b,
                          float* __restrict__ out)
{
    const int row = blockIdx.x, tid = threadIdx.x;  // 128 threads
    const size_t base = (size_t)row * D_MODEL;
    float4 v = *(const float4*)&g_pre[base + tid * 4];
    float s = v.x + v.y + v.z + v.w;
    float s2 = v.x * v.x + v.y * v.y + v.z * v.z + v.w * v.w;
    __shared__ float rs[4], rs2[4];
    #pragma unroll
    for (int o = 16; o > 0; o >>= 1) {
        s  += __shfl_xor_sync(0xffffffffu, s, o);
        s2 += __shfl_xor_sync(0xffffffffu, s2, o);
    }
    if ((tid & 31) == 0) { rs[tid >> 5] = s; rs2[tid >> 5] = s2; }
    __syncthreads();
    float ts = rs[0] + rs[1] + rs[2] + rs[3];
    float ts2 = rs2[0] + rs2[1] + rs2[2] + rs2[3];
    float mu = ts * (1.f / D_MODEL);
    float var = ts2 * (1.f / D_MODEL) - mu * mu;
    float isd = rsqrtf(var + 1e-5f);
    float4 wv = *(const float4*)&ln_w[tid * 4];
    float4 bv = *(const float4*)&ln_b[tid * 4];
    float4 o;
    o.x = (v.x - mu) * isd * wv.x + bv.x;
    o.y = (v.y - mu) * isd * wv.y + bv.y;
    o.z = (v.z - mu) * isd * wv.z + bv.z;
    o.w = (v.w - mu) * isd * wv.w + bv.w;
    *(float4*)&out[base + tid * 4] = o;
}

// ---------------- orchestration ---------------------------------------------------
extern "C" void kernel_launch(void* const* d_in, const int* in_sizes, int n_in,
                              void* d_out, int out_size)
{
    const float* x      = (const float*)d_in[0];
    const float* f_in_proj  = (const float*)d_in[1];
    const float* f_conv_w   = (const float*)d_in[2];
    const float* f_conv_b   = (const float*)d_in[3];
    const float* f_dt_bias  = (const float*)d_in[4];
    const float* f_A_log    = (const float*)d_in[5];
    const float* f_D        = (const float*)d_in[6];
    const float* f_norm_w   = (const float*)d_in[7];
    const float* f_out_proj = (const float*)d_in[8];
    const float* b_in_proj  = (const float*)d_in[9];
    const float* b_conv_w   = (const float*)d_in[10];
    const float* b_conv_b   = (const float*)d_in[11];
    const float* b_dt_bias  = (const float*)d_in[12];
    const float* b_A_log    = (const float*)d_in[13];
    const float* b_D        = (const float*)d_in[14];
    const float* b_norm_w   = (const float*)d_in[15];
    const float* b_out_proj = (const float*)d_in[16];
    const float* proj_w = (const float*)d_in[17];
    const float* proj_b = (const float*)d_in[18];
    const float* ln_w   = (const float*)d_in[19];
    const float* ln_b   = (const float*)d_in[20];

    float *zx0, *zx1, *pre;
    __half *x16, *wip16, *wop16, *wpr16, *y16, *do16;
    cudaGetSymbolAddress((void**)&zx0, g_zx);
    zx1 = zx0 + (size_t)BL * D_IN_PROJ;
    cudaGetSymbolAddress((void**)&pre, g_pre);
    cudaGetSymbolAddress((void**)&x16, g_x16);
    cudaGetSymbolAddress((void**)&wip16, g_wip16);
    cudaGetSymbolAddress((void**)&wop16, g_wop16);
    cudaGetSymbolAddress((void**)&wpr16, g_wpr16);
    cudaGetSymbolAddress((void**)&y16, g_y16);
    cudaGetSymbolAddress((void**)&do16, g_do16);

    cudaFuncSetAttribute(gemm_f16, cudaFuncAttributeMaxDynamicSharedMemorySize, GT_SMEM);

    // fp32 -> fp16 conversions (x + all GEMM weights)
    f2h_kernel<<<2048, 256>>>(x, x16, BL * D_MODEL / 4);
    f2h_kernel<<<256, 256>>>(f_in_proj, wip16, D_IN_PROJ * D_MODEL / 4);
    f2h_kernel<<<256, 256>>>(b_in_proj, wip16 + (size_t)D_IN_PROJ * D_MODEL,
                             D_IN_PROJ * D_MODEL / 4);
    f2h_kernel<<<128, 256>>>(f_out_proj, wop16, D_MODEL * D_INNER / 4);
    f2h_kernel<<<128, 256>>>(b_out_proj, wop16 + (size_t)D_MODEL * D_INNER,
                             D_MODEL * D_INNER / 4);
    f2h_kernel<<<128, 256>>>(proj_w, wpr16, D_MODEL * D_INNER / 4);

    // in_proj both dirs: zx[z] = x16(flip if z) @ wip16[z]^T  -> fp32
    gemm_f16<<<dim3((D_IN_PROJ + 127) / 128, BL / 256, 2), 256, GT_SMEM>>>(
        x16, x16, D_MODEL, wip16, wip16 + (size_t)D_IN_PROJ * D_MODEL,
        zx0, zx1, D_IN_PROJ, 0,
        D_IN_PROJ, D_MODEL, 0b10, 0, 0, nullptr, nullptr);

    conv_silu_kernel<<<dim3(BL, 2), 256>>>(f_conv_w, b_conv_w, f_conv_b, b_conv_b,
                                           f_dt_bias, b_dt_bias);

    scanA_kernel<<<dim3(NC, NHEADS, 2 * B_SZ), 256>>>(f_A_log, b_A_log);
    scanMid_kernel<<<dim3(NHEADS, B_SZ, 2), 256>>>();
    scanB_kernel<<<dim3(NC, NHEADS, 2 * B_SZ), 256>>>(f_A_log, b_A_log, f_D, b_D);

    gate_rms_kernel<<<dim3(BL, 2), 256>>>(f_norm_w, b_norm_w);

    // out_proj both dirs -> g_do16 halves (fp16), bwd written time-flipped
    gemm_f16<<<dim3(D_MODEL / 128, BL / 256, 2), 256, GT_SMEM>>>(
        y16, y16 + (size_t)BL * D_INNER, D_INNER,
        wop16, wop16 + (size_t)D_MODEL * D_INNER,
        do16, do16, D_INNER, D_MODEL,
        D_MODEL, D_INNER, 0, 0b10, 1, nullptr, nullptr);

    // pre = x + proj_b + do16 @ wpr16^T  -> fp32
    gemm_f16<<<dim3(D_MODEL / 128, BL / 256, 1), 256, GT_SMEM>>>(
        do16, do16, D_INNER, wpr16, wpr16,
        pre, pre, D_MODEL, 0,
        D_MODEL, D_INNER, 0, 0, 0, proj_b, x);

    ln_kernel<<<BL, 128>>>(ln_w, ln_b, (float*)d_out);
}

// round 8
// speedup vs baseline: 3.8113x; 1.0775x over previous
#include <cuda_runtime.h>
#include <cuda_fp16.h>
#include <cstdint>

#define B_SZ    8
#define L_SEQ   4096
#define D_MODEL 512
#define D_INNER 1024
#define NHEADS  16
#define HEADDIM 64
#define D_STATE 16
#define CONV_DIM 1056
#define D_IN_PROJ 2096
#define BL      (B_SZ * L_SEQ)
#define CS      64
#define NC      (L_SEQ / CS)

// ---------------- scratch (device globals; no allocation allowed) ----------------
__device__ float g_zx[2][(size_t)BL * D_IN_PROJ];
__device__ float g_dt[2][(size_t)BL * NHEADS];
__device__ float g_y[2][(size_t)BL * D_INNER];
__device__ float g_pre[(size_t)BL * D_MODEL];
__device__ float g_hstate[2][(size_t)B_SZ * NHEADS * NC * 1024];
__device__ float g_P[2][B_SZ * NHEADS * NC];

__device__ __half g_x16[(size_t)BL * D_MODEL];
__device__ __half g_wip16[2][(size_t)D_IN_PROJ * D_MODEL];
__device__ __half g_wop16[2][(size_t)D_MODEL * D_INNER];
__device__ __half g_wpr16[(size_t)D_MODEL * D_INNER];
__device__ __half g_y16[2][(size_t)BL * D_INNER];
__device__ __half g_do16[(size_t)BL * D_INNER];

__device__ __forceinline__ int fliprow(int r) {
    return (r & ~(L_SEQ - 1)) | ((L_SEQ - 1) - (r & (L_SEQ - 1)));
}
__device__ __forceinline__ void cpa16(uint32_t dst, const void* src, int sz) {
    asm volatile("cp.async.cg.shared.global [%0], [%1], 16, %2;"
                 :: "r"(dst), "l"(src), "r"(sz));
}
#define CP_COMMIT() asm volatile("cp.async.commit_group;" ::: "memory")
#define CP_WAIT1()  asm volatile("cp.async.wait_group 1;" ::: "memory")

// ---------------- fp32 -> fp16 convert (grid-stride, float4) ---------------------
__global__ void f2h_kernel(const float* __restrict__ src, __half* __restrict__ dst, int n4)
{
    for (int i = blockIdx.x * blockDim.x + threadIdx.x; i < n4; i += gridDim.x * blockDim.x) {
        float4 v = *(const float4*)(src + (size_t)i * 4);
        __half2* d = (__half2*)(dst + (size_t)i * 4);
        d[0] = __floats2half2_rn(v.x, v.y);
        d[1] = __floats2half2_rn(v.z, v.w);
    }
}

// ============ fp16 mma.sync GEMM: C = A[M,K] @ W[N,K]^T (+bias +resid) ==========
// CTA tile 128x128, BK=64, 3-stage cp.async, 8 warps (4m x 2n), warp tile 32x64,
// mma m16n8k16.f16 + fp32 accumulate. 2 CTAs/SM for stall filling.
#define GT_STAGES 3
#define GT_ASZ 16384            /* 128 rows * 128B */
#define GT_STG (2 * GT_ASZ)
#define GT_SMEM (GT_STAGES * GT_STG + 1024)

__global__ void __launch_bounds__(256, 2)
gemm_f16(const __half* __restrict__ A0, const __half* __restrict__ A1, int lda,
         const __half* __restrict__ W0, const __half* __restrict__ W1,
         void* C0v, void* C1v, int ldc, int ccolstep,
         int N, int K, int flipAmask, int flipCmask, int halfOut,
         const float* __restrict__ bias,
         const float* __restrict__ resid)
{
    extern __shared__ char dsm[];
    const uint32_t sb_raw = (uint32_t)__cvta_generic_to_shared(dsm);
    const uint32_t sb = (sb_raw + 1023u) & ~1023u;

    const int z = blockIdx.z;
    const __half* A = z ? A1 : A0;
    const __half* W = z ? W1 : W0;
    void* Cv = z ? C1v : C0v;
    const int ccol = z * ccolstep;
    const int flipA = (flipAmask >> z) & 1;
    const int flipC = (flipCmask >> z) & 1;

    const int tid = threadIdx.x;
    const int l   = tid & 31;
    const int w   = tid >> 5;
    const int wm  = w >> 1;                 // 0..3  (32 rows each)
    const int wn  = w & 1;                  // 0..1  (64 cols each)
    const int m0  = blockIdx.y * 128;
    const int n0  = blockIdx.x * 128;

    const int lr = l & 15;
    const int lc = l >> 4;
    const int lx = lr & 7;

    float acc[2][8][4];
    #pragma unroll
    for (int mi = 0; mi < 2; mi++)
        #pragma unroll
        for (int ni = 0; ni < 8; ni++)
            #pragma unroll
            for (int k = 0; k < 4; k++) acc[mi][ni][k] = 0.f;

    auto issue = [&](int s) {
        const int k0 = s * 64;
        const uint32_t base = sb + (s % GT_STAGES) * GT_STG;
        #pragma unroll
        for (int i = 0; i < 4; i++) {
            int q = tid + i * 256;
            int rr = q >> 3, ch = q & 7;
            int off = rr * 128 + ((ch ^ (rr & 7)) << 4);
            int r = m0 + rr;
            int ar = flipA ? fliprow(r) : r;
            cpa16(base + off, A + (size_t)ar * lda + k0 + ch * 8, 16);
        }
        #pragma unroll
        for (int i = 0; i < 4; i++) {
            int q = tid + i * 256;
            int rr = q >> 3, ch = q & 7;
            int off = rr * 128 + ((ch ^ (rr & 7)) << 4);
            int n = n0 + rr;
            cpa16(base + GT_ASZ + off,
                  W + (size_t)(n < N ? n : 0) * K + k0 + ch * 8, (n < N) ? 16 : 0);
        }
    };
    auto compute = [&](int s) {
        const uint32_t Ab = sb + s * GT_STG;
        const uint32_t Bb = Ab + GT_ASZ;
        #pragma unroll
        for (int ks = 0; ks < 4; ks++) {
            const int chsel = ((ks << 1) | lc) ^ lx;
            uint32_t af[2][4];
            #pragma unroll
            for (int mi = 0; mi < 2; mi++) {
                uint32_t ad = Ab + (wm * 32 + mi * 16 + lr) * 128 + (chsel << 4);
                asm volatile("ldmatrix.sync.aligned.m8n8.x4.shared.b16 {%0,%1,%2,%3}, [%4];"
                    : "=r"(af[mi][0]), "=r"(af[mi][1]), "=r"(af[mi][2]), "=r"(af[mi][3])
                    : "r"(ad));
            }
            uint32_t bf[8][2];
            #pragma unroll
            for (int p = 0; p < 4; p++) {
                uint32_t bd = Bb + (wn * 64 + p * 16 + lr) * 128 + (chsel << 4);
                uint32_t q0, q1, q2, q3;
                asm volatile("ldmatrix.sync.aligned.m8n8.x4.shared.b16 {%0,%1,%2,%3}, [%4];"
                    : "=r"(q0), "=r"(q1), "=r"(q2), "=r"(q3) : "r"(bd));
                bf[2 * p][0] = q0;     bf[2 * p][1] = q2;
                bf[2 * p + 1][0] = q1; bf[2 * p + 1][1] = q3;
            }
            #pragma unroll
            for (int mi = 0; mi < 2; mi++)
                #pragma unroll
                for (int ni = 0; ni < 8; ni++) {
                    asm volatile(
                        "mma.sync.aligned.m16n8k16.row.col.f32.f16.f16.f32 "
                        "{%0,%1,%2,%3},{%4,%5,%6,%7},{%8,%9},{%0,%1,%2,%3};"
                        : "+f"(acc[mi][ni][0]), "+f"(acc[mi][ni][1]),
                          "+f"(acc[mi][ni][2]), "+f"(acc[mi][ni][3])
                        : "r"(af[mi][0]), "r"(af[mi][1]), "r"(af[mi][2]), "r"(af[mi][3]),
                          "r"(bf[ni][0]), "r"(bf[ni][1]));
                }
        }
    };

    const int KT = K / 64;
    issue(0); CP_COMMIT();
    issue(1); CP_COMMIT();
    for (int kt = 0; kt < KT; kt++) {
        CP_WAIT1();
        __syncthreads();
        if (kt + 2 < KT) issue(kt + 2);
        CP_COMMIT();
        compute(kt % GT_STAGES);
    }

    // epilogue
    #pragma unroll
    for (int mi = 0; mi < 2; mi++) {
        #pragma unroll
        for (int half = 0; half < 2; half++) {
            int r = m0 + wm * 32 + mi * 16 + (l >> 2) + half * 8;
            int cr = flipC ? fliprow(r) : r;
            const float* rp = resid + (size_t)cr * ldc + ccol;
            #pragma unroll
            for (int ni = 0; ni < 8; ni++) {
                int col = n0 + wn * 64 + ni * 8 + ((l & 3) << 1);
                if (col < N) {
                    float v0 = acc[mi][ni][half * 2 + 0];
                    float v1 = acc[mi][ni][half * 2 + 1];
                    if (bias)  { v0 += bias[col]; v1 += bias[col + 1]; }
                    if (resid) { v0 += rp[col];   v1 += rp[col + 1]; }
                    if (halfOut) {
                        __half2* hp = (__half2*)((__half*)Cv + (size_t)cr * ldc + ccol + col);
                        *hp = __floats2half2_rn(v0, v1);
                    } else {
                        float* cp = (float*)Cv + (size_t)cr * ldc + ccol;
                        *(float2*)(cp + col) = make_float2(v0, v1);
                    }
                }
            }
        }
    }
}

// helper: silu
__device__ __forceinline__ float siluf(float v) { return v / (1.f + expf(-v)); }

// ======== fused conv + chunked scan pass A (local from zero) =====================
// stages zx slice, applies 4-tap causal conv + silu in smem, then scans.
__global__ void __launch_bounds__(256)
scanA_kernel(const float* __restrict__ Al0, const float* __restrict__ Al1,
             const float* __restrict__ cw0, const float* __restrict__ cw1,
             const float* __restrict__ cb0, const float* __restrict__ cb1,
             const float* __restrict__ db0, const float* __restrict__ db1)
{
    const int c = blockIdx.x, h = blockIdx.y;
    const int b = blockIdx.z & (B_SZ - 1), dir = blockIdx.z >> 3;
    const int tid = threadIdx.x;
    const int p = tid >> 2, q = tid & 3;
    const float Aneg = -expf((dir ? Al1 : Al0)[h]);
    const float* conv_w  = dir ? cw1 : cw0;
    const float* conv_b  = dir ? cb1 : cb0;
    const float* dt_bias = dir ? db1 : db0;
    const float* zx = g_zx[dir];

    __shared__ float szx[CS + 3][80];
    __shared__ float sx[CS][64];
    __shared__ float sB[CS][16];
    __shared__ float sdt[CS];
    __shared__ float sdA[CS];
    __shared__ float scw[80 * 4];
    __shared__ float scb[80];

    const int l0 = c * CS;
    const size_t rowbase = (size_t)b * L_SEQ + l0;

    for (int idx = tid; idx < (CS + 3) * 80; idx += 256) {
        int s = idx / 80, ch = idx % 80;
        int ll = l0 + s - 3;
        int zc = (ch < 64) ? (D_INNER + h * 64 + ch) : (D_INNER + 1024 + (ch - 64));
        szx[s][ch] = (ll >= 0) ? zx[((size_t)b * L_SEQ + ll) * D_IN_PROJ + zc] : 0.f;
    }
    if (tid < 80) {
        int cc = (tid < 64) ? (h * 64 + tid) : (1024 + (tid - 64));
        scb[tid] = conv_b[cc];
        #pragma unroll
        for (int k = 0; k < 4; k++) scw[tid * 4 + k] = conv_w[cc * 4 + k];
    }
    if (tid < CS) {
        float raw = zx[(rowbase + tid) * D_IN_PROJ + D_INNER + CONV_DIM + h] + dt_bias[h];
        float sp = (raw > 20.f) ? raw : log1pf(expf(raw));
        sdt[tid] = sp;
        sdA[tid] = expf(sp * Aneg);
    }
    __syncthreads();

    for (int idx = tid; idx < CS * 80; idx += 256) {
        int s = idx / 80, ch = idx % 80;
        float v = scb[ch];
        #pragma unroll
        for (int k = 0; k < 4; k++) v += szx[s + k][ch] * scw[ch * 4 + k];
        v = siluf(v);
        if (ch < 64) sx[s][ch] = v; else sB[s][ch - 64] = v;
    }
    __syncthreads();

    float h0 = 0.f, h1 = 0.f, h2 = 0.f, h3 = 0.f;
    #pragma unroll 4
    for (int s = 0; s < CS; s++) {
        float dA = sdA[s];
        float coef = sdt[s] * sx[s][p];
        float4 Bv = *(const float4*)&sB[s][q * 4];
        h0 = h0 * dA + coef * Bv.x;
        h1 = h1 * dA + coef * Bv.y;
        h2 = h2 * dA + coef * Bv.z;
        h3 = h3 * dA + coef * Bv.w;
    }
    size_t base = (((size_t)(b * NHEADS + h) * NC + c) << 10) + tid * 4;
    *(float4*)&g_hstate[dir][base] = make_float4(h0, h1, h2, h3);
    if (tid == 0) {
        float P = 1.f;
        for (int s = 0; s < CS; s++) P *= sdA[s];
        g_P[dir][(b * NHEADS + h) * NC + c] = P;
    }
}

// ======== chunked scan: middle combine (sequential over 64 chunks, prefetched) ==
__global__ void __launch_bounds__(256)
scanMid_kernel()
{
    const int h = blockIdx.x, b = blockIdx.y, dir = blockIdx.z;
    const int tid = threadIdx.x;
    float* hs = g_hstate[dir];
    const size_t base = ((size_t)(b * NHEADS + h) * NC << 10) + tid * 4;
    __shared__ float sP[NC];
    if (tid < NC) sP[tid] = g_P[dir][(b * NHEADS + h) * NC + tid];
    __syncthreads();
    float4 nxt = *(float4*)&hs[base];
    float4 run = make_float4(0.f, 0.f, 0.f, 0.f);
    for (int c = 0; c < NC; c++) {
        float4 endv = nxt;
        if (c + 1 < NC) nxt = *(float4*)&hs[base + ((size_t)(c + 1) << 10)];
        *(float4*)&hs[base + ((size_t)c << 10)] = run;
        float P = sP[c];
        run.x = P * run.x + endv.x;
        run.y = P * run.y + endv.y;
        run.z = P * run.z + endv.z;
        run.w = P * run.w + endv.w;
    }
}

// ======== fused conv + chunked scan pass B (seeded, emit y) =====================
// dynamic smem layout (floats):
//   szx 67*96 (reused as sy 64*64 after conv) | sx 64*64 | sB 64*16 | sC 64*16 |
//   sdt 64 | sdA 64 | scw 96*4 | scb 96
#define SB_SMEM ((67 * 96 + 64 * 64 + 1024 + 1024 + 64 + 64 + 384 + 96) * 4)

__global__ void __launch_bounds__(256)
scanB_kernel(const float* __restrict__ Al0, const float* __restrict__ Al1,
             const float* __restrict__ Dp0, const float* __restrict__ Dp1,
             const float* __restrict__ cw0, const float* __restrict__ cw1,
             const float* __restrict__ cb0, const float* __restrict__ cb1,
             const float* __restrict__ db0, const float* __restrict__ db1)
{
    extern __shared__ float sm[];
    float* szx = sm;                       // [67][96]
    float* sx  = sm + 67 * 96;             // [64][64]
    float* sB  = sx + 64 * 64;             // [64][16]
    float* sC  = sB + 1024;                // [64][16]
    float* sdt = sC + 1024;                // [64]
    float* sdA = sdt + 64;                 // [64]
    float* scw = sdA + 64;                 // [96*4]
    float* scb = scw + 384;                // [96]
    float* sy  = szx;                      // reuse after conv phase

    const int c = blockIdx.x, h = blockIdx.y;
    const int b = blockIdx.z & (B_SZ - 1), dir = blockIdx.z >> 3;
    const int tid = threadIdx.x;
    const int p = tid >> 2, q = tid & 3;
    const float Aneg = -expf((dir ? Al1 : Al0)[h]);
    const float Dh = (dir ? Dp1 : Dp0)[h];
    const float* conv_w  = dir ? cw1 : cw0;
    const float* conv_b  = dir ? cb1 : cb0;
    const float* dt_bias = dir ? db1 : db0;
    const float* zx = g_zx[dir];

    const int l0 = c * CS;
    const size_t rowbase = (size_t)b * L_SEQ + l0;

    for (int idx = tid; idx < (CS + 3) * 96; idx += 256) {
        int s = idx / 96, ch = idx % 96;
        int ll = l0 + s - 3;
        int zc = (ch < 64) ? (D_INNER + h * 64 + ch) : (D_INNER + 1024 + (ch - 64));
        szx[s * 96 + ch] = (ll >= 0) ? zx[((size_t)b * L_SEQ + ll) * D_IN_PROJ + zc] : 0.f;
    }
    if (tid < 96) {
        int cc = (tid < 64) ? (h * 64 + tid) : (1024 + (tid - 64));
        scb[tid] = conv_b[cc];
        #pragma unroll
        for (int k = 0; k < 4; k++) scw[tid * 4 + k] = conv_w[cc * 4 + k];
    }
    if (tid < CS) {
        float raw = zx[(rowbase + tid) * D_IN_PROJ + D_INNER + CONV_DIM + h] + dt_bias[h];
        float sp = (raw > 20.f) ? raw : log1pf(expf(raw));
        sdt[tid] = sp;
        sdA[tid] = expf(sp * Aneg);
    }
    float4 hin = *(float4*)&g_hstate[dir][(((size_t)(b * NHEADS + h) * NC + c) << 10) + tid * 4];
    __syncthreads();

    for (int idx = tid; idx < CS * 96; idx += 256) {
        int s = idx / 96, ch = idx % 96;
        float v = scb[ch];
        #pragma unroll
        for (int k = 0; k < 4; k++) v += szx[(s + k) * 96 + ch] * scw[ch * 4 + k];
        v = siluf(v);
        if (ch < 64) sx[s * 64 + ch];
        if (ch < 64) sx[s * 64 + ch] = v;
        else if (ch < 80) sB[s * 16 + (ch - 64)] = v;
        else sC[s * 16 + (ch - 80)] = v;
    }
    __syncthreads();

    float h0 = hin.x, h1 = hin.y, h2 = hin.z, h3 = hin.w;
    for (int s = 0; s < CS; s++) {
        float dA = sdA[s];
        float xv = sx[s * 64 + p];
        float coef = sdt[s] * xv;
        float4 Bv = *(const float4*)&sB[s * 16 + q * 4];
        float4 Cv = *(const float4*)&sC[s * 16 + q * 4];
        h0 = h0 * dA + coef * Bv.x;
        h1 = h1 * dA + coef * Bv.y;
        h2 = h2 * dA + coef * Bv.z;
        h3 = h3 * dA + coef * Bv.w;
        float yp = h0 * Cv.x + h1 * Cv.y + h2 * Cv.z + h3 * Cv.w;
        yp += __shfl_xor_sync(0xffffffffu, yp, 1);
        yp += __shfl_xor_sync(0xffffffffu, yp, 2);
        if (q == 0) sy[s * 64 + p] = yp + Dh * xv;
    }
    __syncthreads();
    for (int idx = tid; idx < CS * 64; idx += 256) {
        int s = idx >> 6, pp = idx & 63;
        g_y[dir][(rowbase + s) * D_INNER + h * 64 + pp] = sy[s * 64 + pp];
    }
}

// ------- y *= silu(z); RMSNorm(y) * norm_w; emit fp16 for out_proj GEMM ----------
__global__ void gate_rms_kernel(const float* __restrict__ nw0, const float* __restrict__ nw1)
{
    const int row = blockIdx.x, dir = blockIdx.y, tid = threadIdx.x;
    const float* norm_w = dir ? nw1 : nw0;
    const float* yp = &g_y[dir][(size_t)row * D_INNER + tid * 4];
    const float* zp = &g_zx[dir][(size_t)row * D_IN_PROJ + tid * 4];
    float4 yv = *(const float4*)yp;
    float4 zv = *(const float4*)zp;
    yv.x *= zv.x / (1.f + expf(-zv.x));
    yv.y *= zv.y / (1.f + expf(-zv.y));
    yv.z *= zv.z / (1.f + expf(-zv.z));
    yv.w *= zv.w / (1.f + expf(-zv.w));
    float ss = yv.x * yv.x + yv.y * yv.y + yv.z * yv.z + yv.w * yv.w;
    __shared__ float red[8];
    #pragma unroll
    for (int o = 16; o > 0; o >>= 1) ss += __shfl_xor_sync(0xffffffffu, ss, o);
    if ((tid & 31) == 0) red[tid >> 5] = ss;
    __syncthreads();
    float tot = red[0] + red[1] + red[2] + red[3] + red[4] + red[5] + red[6] + red[7];
    float sc = rsqrtf(tot * (1.f / D_INNER) + 1e-5f);
    float4 nv = *(const float4*)&norm_w[tid * 4];
    __half2* hp = (__half2*)&g_y16[dir][(size_t)row * D_INNER + tid * 4];
    hp[0] = __floats2half2_rn(yv.x * sc * nv.x, yv.y * sc * nv.y);
    hp[1] = __floats2half2_rn(yv.z * sc * nv.z, yv.w * sc * nv.w);
}

// ---------------- final LayerNorm over 512 -> d_out ------------------------------
__global__ void ln_kernel(const float* __restrict__ ln_w, const float* __restrict__ ln_b,
                          float* __restrict__ out)
{
    const int row = blockIdx.x, tid = threadIdx.x;  // 128 threads
    const size_t base = (size_t)row * D_MODEL;
    float4 v = *(const float4*)&g_pre[base + tid * 4];
    float s = v.x + v.y + v.z + v.w;
    float s2 = v.x * v.x + v.y * v.y + v.z * v.z + v.w * v.w;
    __shared__ float rs[4], rs2[4];
    #pragma unroll
    for (int o = 16; o > 0; o >>= 1) {
        s  += __shfl_xor_sync(0xffffffffu, s, o);
        s2 += __shfl_xor_sync(0xffffffffu, s2, o);
    }
    if ((tid & 31) == 0) { rs[tid >> 5] = s; rs2[tid >> 5] = s2; }
    __syncthreads();
    float ts = rs[0] + rs[1] + rs[2] + rs[3];
    float ts2 = rs2[0] + rs2[1] + rs2[2] + rs2[3];
    float mu = ts * (1.f / D_MODEL);
    float var = ts2 * (1.f / D_MODEL) - mu * mu;
    float isd = rsqrtf(var + 1e-5f);
    float4 wv = *(const float4*)&ln_w[tid * 4];
    float4 bv = *(const float4*)&ln_b[tid * 4];
    float4 o;
    o.x = (v.x - mu) * isd * wv.x + bv.x;
    o.y = (v.y - mu) * isd * wv.y + bv.y;
    o.z = (v.z - mu) * isd * wv.z + bv.z;
    o.w = (v.w - mu) * isd * wv.w + bv.w;
    *(float4*)&out[base + tid * 4] = o;
}

// ---------------- orchestration ---------------------------------------------------
extern "C" void kernel_launch(void* const* d_in, const int* in_sizes, int n_in,
                              void* d_out, int out_size)
{
    const float* x      = (const float*)d_in[0];
    const float* f_in_proj  = (const float*)d_in[1];
    const float* f_conv_w   = (const float*)d_in[2];
    const float* f_conv_b   = (const float*)d_in[3];
    const float* f_dt_bias  = (const float*)d_in[4];
    const float* f_A_log    = (const float*)d_in[5];
    const float* f_D        = (const float*)d_in[6];
    const float* f_norm_w   = (const float*)d_in[7];
    const float* f_out_proj = (const float*)d_in[8];
    const float* b_in_proj  = (const float*)d_in[9];
    const float* b_conv_w   = (const float*)d_in[10];
    const float* b_conv_b   = (const float*)d_in[11];
    const float* b_dt_bias  = (const float*)d_in[12];
    const float* b_A_log    = (const float*)d_in[13];
    const float* b_D        = (const float*)d_in[14];
    const float* b_norm_w   = (const float*)d_in[15];
    const float* b_out_proj = (const float*)d_in[16];
    const float* proj_w = (const float*)d_in[17];
    const float* proj_b = (const float*)d_in[18];
    const float* ln_w   = (const float*)d_in[19];
    const float* ln_b   = (const float*)d_in[20];

    float *zx0, *zx1, *pre;
    __half *x16, *wip16, *wop16, *wpr16, *y16, *do16;
    cudaGetSymbolAddress((void**)&zx0, g_zx);
    zx1 = zx0 + (size_t)BL * D_IN_PROJ;
    cudaGetSymbolAddress((void**)&pre, g_pre);
    cudaGetSymbolAddress((void**)&x16, g_x16);
    cudaGetSymbolAddress((void**)&wip16, g_wip16);
    cudaGetSymbolAddress((void**)&wop16, g_wop16);
    cudaGetSymbolAddress((void**)&wpr16, g_wpr16);
    cudaGetSymbolAddress((void**)&y16, g_y16);
    cudaGetSymbolAddress((void**)&do16, g_do16);

    cudaFuncSetAttribute(gemm_f16, cudaFuncAttributeMaxDynamicSharedMemorySize, GT_SMEM);
    cudaFuncSetAttribute(scanB_kernel, cudaFuncAttributeMaxDynamicSharedMemorySize, SB_SMEM);

    // fp32 -> fp16 conversions (x + all GEMM weights)
    f2h_kernel<<<2048, 256>>>(x, x16, BL * D_MODEL / 4);
    f2h_kernel<<<256, 256>>>(f_in_proj, wip16, D_IN_PROJ * D_MODEL / 4);
    f2h_kernel<<<256, 256>>>(b_in_proj, wip16 + (size_t)D_IN_PROJ * D_MODEL,
                             D_IN_PROJ * D_MODEL / 4);
    f2h_kernel<<<128, 256>>>(f_out_proj, wop16, D_MODEL * D_INNER / 4);
    f2h_kernel<<<128, 256>>>(b_out_proj, wop16 + (size_t)D_MODEL * D_INNER,
                             D_MODEL * D_INNER / 4);
    f2h_kernel<<<128, 256>>>(proj_w, wpr16, D_MODEL * D_INNER / 4);

    // in_proj both dirs: zx[z] = x16(flip if z) @ wip16[z]^T  -> fp32
    gemm_f16<<<dim3((D_IN_PROJ + 127) / 128, BL / 128, 2), 256, GT_SMEM>>>(
        x16, x16, D_MODEL, wip16, wip16 + (size_t)D_IN_PROJ * D_MODEL,
        zx0, zx1, D_IN_PROJ, 0,
        D_IN_PROJ, D_MODEL, 0b10, 0, 0, nullptr, nullptr);

    // fused conv + scan
    scanA_kernel<<<dim3(NC, NHEADS, 2 * B_SZ), 256>>>(
        f_A_log, b_A_log, f_conv_w, b_conv_w, f_conv_b, b_conv_b, f_dt_bias, b_dt_bias);
    scanMid_kernel<<<dim3(NHEADS, B_SZ, 2), 256>>>();
    scanB_kernel<<<dim3(NC, NHEADS, 2 * B_SZ), 256, SB_SMEM>>>(
        f_A_log, b_A_log, f_D, b_D,
        f_conv_w, b_conv_w, f_conv_b, b_conv_b, f_dt_bias, b_dt_bias);

    gate_rms_kernel<<<dim3(BL, 2), 256>>>(f_norm_w, b_norm_w);

    // out_proj both dirs -> g_do16 halves (fp16), bwd written time-flipped
    gemm_f16<<<dim3(D_MODEL / 128, BL / 128, 2), 256, GT_SMEM>>>(
        y16, y16 + (size_t)BL * D_INNER, D_INNER,
        wop16, wop16 + (size_t)D_MODEL * D_INNER,
        do16, do16, D_INNER, D_MODEL,
        D_MODEL, D_INNER, 0, 0b10, 1, nullptr, nullptr);

    // pre = x + proj_b + do16 @ wpr16^T  -> fp32
    gemm_f16<<<dim3(D_MODEL / 128, BL / 128, 1), 256, GT_SMEM>>>(
        do16, do16, D_INNER, wpr16, wpr16,
        pre, pre, D_MODEL, 0,
        D_MODEL, D_INNER, 0, 0, 0, proj_b, x);

    ln_kernel<<<BL, 128>>>(ln_w, ln_b, (float*)d_out);
}

// round 9
// speedup vs baseline: 4.0143x; 1.0532x over previous
#include <cuda_runtime.h>
#include <cuda_fp16.h>
#include <cstdint>

#define B_SZ    8
#define L_SEQ   4096
#define D_MODEL 512
#define D_INNER 1024
#define NHEADS  16
#define HEADDIM 64
#define D_STATE 16
#define CONV_DIM 1056
#define D_IN_PROJ 2096
#define BL      (B_SZ * L_SEQ)
#define CS      64
#define NC      (L_SEQ / CS)
#define AUXZ    ((size_t)BL * 16)

// ---------------- scratch (device globals; no allocation allowed) ----------------
__device__ __half g_zx16[2][(size_t)BL * D_IN_PROJ];   // in_proj out (fp16)
__device__ float g_dtraw[2][(size_t)BL * 16];          // dt pre-softplus (fp32)
__device__ float g_y[2][(size_t)BL * D_INNER];
__device__ float g_pre[(size_t)BL * D_MODEL];
__device__ float g_hstate[2][(size_t)B_SZ * NHEADS * NC * 1024];
__device__ float g_P[2][B_SZ * NHEADS * NC];

__device__ __half g_x16[(size_t)BL * D_MODEL];
__device__ __half g_wip16[2][(size_t)D_IN_PROJ * D_MODEL];
__device__ __half g_wpr16[(size_t)D_MODEL * D_INNER];
__device__ __half g_wofT16[2][(size_t)D_INNER * D_MODEL]; // out_proj^T fp16
__device__ __half g_wcomb16[(size_t)D_MODEL * 2 * D_INNER]; // [512][2048]
__device__ __half g_y16[2][(size_t)BL * D_INNER];

__device__ __forceinline__ int fliprow(int r) {
    return (r & ~(L_SEQ - 1)) | ((L_SEQ - 1) - (r & (L_SEQ - 1)));
}
__device__ __forceinline__ void cpa16(uint32_t dst, const void* src, int sz) {
    asm volatile("cp.async.cg.shared.global [%0], [%1], 16, %2;"
                 :: "r"(dst), "l"(src), "r"(sz));
}
#define CP_COMMIT() asm volatile("cp.async.commit_group;" ::: "memory")
#define CP_WAIT1()  asm volatile("cp.async.wait_group 1;" ::: "memory")

// ---------------- fp32 -> fp16 convert (grid-stride, float4) ---------------------
__global__ void f2h_kernel(const float* __restrict__ src, __half* __restrict__ dst, int n4)
{
    for (int i = blockIdx.x * blockDim.x + threadIdx.x; i < n4; i += gridDim.x * blockDim.x) {
        float4 v = *(const float4*)(src + (size_t)i * 4);
        __half2* d = (__half2*)(dst + (size_t)i * 4);
        d[0] = __floats2half2_rn(v.x, v.y);
        d[1] = __floats2half2_rn(v.z, v.w);
    }
}

// ------------- transpose fp32 [512][1024] -> fp16 [1024][512] --------------------
__global__ void tr_f2h_kernel(const float* __restrict__ s0, const float* __restrict__ s1,
                              __half* __restrict__ d0, __half* __restrict__ d1)
{
    const float* src = blockIdx.z ? s1 : s0;
    __half* dst = blockIdx.z ? d1 : d0;
    __shared__ float t[32][33];
    int c0 = blockIdx.x * 32, r0 = blockIdx.y * 32;
    int tx = threadIdx.x, ty = threadIdx.y;   // 32 x 8
    #pragma unroll
    for (int i = 0; i < 4; i++)
        t[ty + i * 8][tx] = src[(size_t)(r0 + ty + i * 8) * D_INNER + c0 + tx];
    __syncthreads();
    #pragma unroll
    for (int i = 0; i < 4; i++)
        dst[(size_t)(c0 + ty + i * 8) * D_MODEL + r0 + tx] =
            __float2half_rn(t[tx][ty + i * 8]);
}

// ============ fp16 mma.sync GEMM: C = A[M,K] @ W[N,K]^T (+bias +resid) ==========
// CTA tile 128x128, BK=64, 3-stage cp.async, 8 warps (4m x 2n), warp tile 32x64.
// grid.z selects direction set; ksplit<K enables dual-A k-stitching (z==0 only).
#define GT_STAGES 3
#define GT_ASZ 16384
#define GT_STG (2 * GT_ASZ)
#define GT_SMEM (GT_STAGES * GT_STG + 1024)

__global__ void __launch_bounds__(256, 2)
gemm_f16(const __half* __restrict__ A0, const __half* __restrict__ A1, int lda,
         const __half* __restrict__ W0, const __half* __restrict__ W1, int Wld,
         void* C0v, void* C1v, int ldc, int ccolstep,
         int N, int K, int ksplit,
         int flipAmask, int flipCmask, int halfOut,
         const float* __restrict__ bias,
         const float* __restrict__ resid,
         float* __restrict__ aux, int auxlo)
{
    extern __shared__ char dsm[];
    const uint32_t sb_raw = (uint32_t)__cvta_generic_to_shared(dsm);
    const uint32_t sb = (sb_raw + 1023u) & ~1023u;

    const int z = blockIdx.z;
    const int dual = (ksplit < K);
    const __half* Aa = dual ? A0 : (z ? A1 : A0);
    const __half* W = z ? W1 : W0;
    void* Cv = z ? C1v : C0v;
    const int ccol = z * ccolstep;
    const int flip_a = dual ? (flipAmask & 1) : ((flipAmask >> z) & 1);
    const int flip_b = (flipAmask >> 1) & 1;
    const int flipC = (flipCmask >> z) & 1;
    if (aux) aux += (size_t)z * AUXZ;

    const int tid = threadIdx.x;
    const int l   = tid & 31;
    const int w   = tid >> 5;
    const int wm  = w >> 1;
    const int wn  = w & 1;
    const int m0  = blockIdx.y * 128;
    const int n0  = blockIdx.x * 128;

    const int lr = l & 15;
    const int lc = l >> 4;
    const int lx = lr & 7;

    // cp.async row precompute
    int arowA[4], arowB[4];
    #pragma unroll
    for (int i = 0; i < 4; i++) {
        int rr = (tid + i * 256) >> 3;
        int r = m0 + rr;
        arowA[i] = flip_a ? fliprow(r) : r;
        arowB[i] = flip_b ? fliprow(r) : r;
    }

    float acc[2][8][4];
    #pragma unroll
    for (int mi = 0; mi < 2; mi++)
        #pragma unroll
        for (int ni = 0; ni < 8; ni++)
            #pragma unroll
            for (int k = 0; k < 4; k++) acc[mi][ni][k] = 0.f;

    auto issue = [&](int s) {
        const int k0 = s * 64;
        const uint32_t base = sb + (s % GT_STAGES) * GT_STG;
        const __half* Ap = Aa;
        const int* ar = arowA;
        int kk = k0;
        if (dual && k0 >= ksplit) { Ap = A1; ar = arowB; kk = k0 - ksplit; }
        #pragma unroll
        for (int i = 0; i < 4; i++) {
            int q = tid + i * 256;
            int rr = q >> 3, ch = q & 7;
            int off = rr * 128 + ((ch ^ (rr & 7)) << 4);
            cpa16(base + off, Ap + (size_t)ar[i] * lda + kk + ch * 8, 16);
        }
        #pragma unroll
        for (int i = 0; i < 4; i++) {
            int q = tid + i * 256;
            int rr = q >> 3, ch = q & 7;
            int off = rr * 128 + ((ch ^ (rr & 7)) << 4);
            int n = n0 + rr;
            cpa16(base + GT_ASZ + off,
                  W + (size_t)(n < N ? n : 0) * Wld + k0 + ch * 8, (n < N) ? 16 : 0);
        }
    };
    auto compute = [&](int s) {
        const uint32_t Ab = sb + s * GT_STG;
        const uint32_t Bb = Ab + GT_ASZ;
        #pragma unroll
        for (int ks = 0; ks < 4; ks++) {
            const int chsel = ((ks << 1) | lc) ^ lx;
            uint32_t af[2][4];
            #pragma unroll
            for (int mi = 0; mi < 2; mi++) {
                uint32_t ad = Ab + (wm * 32 + mi * 16 + lr) * 128 + (chsel << 4);
                asm volatile("ldmatrix.sync.aligned.m8n8.x4.shared.b16 {%0,%1,%2,%3}, [%4];"
                    : "=r"(af[mi][0]), "=r"(af[mi][1]), "=r"(af[mi][2]), "=r"(af[mi][3])
                    : "r"(ad));
            }
            uint32_t bf[8][2];
            #pragma unroll
            for (int p = 0; p < 4; p++) {
                uint32_t bd = Bb + (wn * 64 + p * 16 + lr) * 128 + (chsel << 4);
                uint32_t q0, q1, q2, q3;
                asm volatile("ldmatrix.sync.aligned.m8n8.x4.shared.b16 {%0,%1,%2,%3}, [%4];"
                    : "=r"(q0), "=r"(q1), "=r"(q2), "=r"(q3) : "r"(bd));
                bf[2 * p][0] = q0;     bf[2 * p][1] = q2;
                bf[2 * p + 1][0] = q1; bf[2 * p + 1][1] = q3;
            }
            #pragma unroll
            for (int mi = 0; mi < 2; mi++)
                #pragma unroll
                for (int ni = 0; ni < 8; ni++) {
                    asm volatile(
                        "mma.sync.aligned.m16n8k16.row.col.f32.f16.f16.f32 "
                        "{%0,%1,%2,%3},{%4,%5,%6,%7},{%8,%9},{%0,%1,%2,%3};"
                        : "+f"(acc[mi][ni][0]), "+f"(acc[mi][ni][1]),
                          "+f"(acc[mi][ni][2]), "+f"(acc[mi][ni][3])
                        : "r"(af[mi][0]), "r"(af[mi][1]), "r"(af[mi][2]), "r"(af[mi][3]),
                          "r"(bf[ni][0]), "r"(bf[ni][1]));
                }
        }
    };

    const int KT = K / 64;
    issue(0); CP_COMMIT();
    issue(1); CP_COMMIT();
    for (int kt = 0; kt < KT; kt++) {
        CP_WAIT1();
        __syncthreads();
        if (kt + 2 < KT) issue(kt + 2);
        CP_COMMIT();
        compute(kt % GT_STAGES);
    }

    // epilogue
    #pragma unroll
    for (int mi = 0; mi < 2; mi++) {
        #pragma unroll
        for (int half = 0; half < 2; half++) {
            int r = m0 + wm * 32 + mi * 16 + (l >> 2) + half * 8;
            int cr = flipC ? fliprow(r) : r;
            const float* rp = resid + (size_t)cr * ldc + ccol;
            #pragma unroll
            for (int ni = 0; ni < 8; ni++) {
                int col = n0 + wn * 64 + ni * 8 + ((l & 3) << 1);
                if (col < N) {
                    float v0 = acc[mi][ni][half * 2 + 0];
                    float v1 = acc[mi][ni][half * 2 + 1];
                    if (bias)  { v0 += bias[col]; v1 += bias[col + 1]; }
                    if (resid) { v0 += rp[col];   v1 += rp[col + 1]; }
                    if (aux && col >= auxlo)
                        *(float2*)(aux + (size_t)cr * 16 + (col - auxlo)) =
                            make_float2(v0, v1);
                    if (halfOut) {
                        __half2* hp = (__half2*)((__half*)Cv + (size_t)cr * ldc + ccol + col);
                        *hp = __floats2half2_rn(v0, v1);
                    } else {
                        float* cp = (float*)Cv + (size_t)cr * ldc + ccol;
                        *(float2*)(cp + col) = make_float2(v0, v1);
                    }
                }
            }
        }
    }
}

// helper: silu
__device__ __forceinline__ float siluf(float v) { return v / (1.f + expf(-v)); }

// ======== fused conv + chunked scan pass A (local from zero) =====================
__global__ void __launch_bounds__(256)
scanA_kernel(const float* __restrict__ Al0, const float* __restrict__ Al1,
             const float* __restrict__ cw0, const float* __restrict__ cw1,
             const float* __restrict__ cb0, const float* __restrict__ cb1,
             const float* __restrict__ db0, const float* __restrict__ db1)
{
    const int c = blockIdx.x, h = blockIdx.y;
    const int b = blockIdx.z & (B_SZ - 1), dir = blockIdx.z >> 3;
    const int tid = threadIdx.x;
    const int p = tid >> 2, q = tid & 3;
    const float Aneg = -expf((dir ? Al1 : Al0)[h]);
    const float* conv_w  = dir ? cw1 : cw0;
    const float* conv_b  = dir ? cb1 : cb0;
    const float* dt_bias = dir ? db1 : db0;
    const __half* zx = g_zx16[dir];

    __shared__ float szx[CS + 3][80];
    __shared__ float sx[CS][64];
    __shared__ float sB[CS][16];
    __shared__ float sdt[CS];
    __shared__ float sdA[CS];
    __shared__ float scw[80 * 4];
    __shared__ float scb[80];

    const int l0 = c * CS;
    const size_t rowbase = (size_t)b * L_SEQ + l0;

    for (int idx = tid; idx < (CS + 3) * 80; idx += 256) {
        int s = idx / 80, ch = idx % 80;
        int ll = l0 + s - 3;
        int zc = (ch < 64) ? (D_INNER + h * 64 + ch) : (D_INNER + 1024 + (ch - 64));
        szx[s][ch] = (ll >= 0)
            ? __half2float(zx[((size_t)b * L_SEQ + ll) * D_IN_PROJ + zc]) : 0.f;
    }
    if (tid < 80) {
        int cc = (tid < 64) ? (h * 64 + tid) : (1024 + (tid - 64));
        scb[tid] = conv_b[cc];
        #pragma unroll
        for (int k = 0; k < 4; k++) scw[tid * 4 + k] = conv_w[cc * 4 + k];
    }
    if (tid < CS) {
        float raw = g_dtraw[dir][(rowbase + tid) * 16 + h] + dt_bias[h];
        float sp = (raw > 20.f) ? raw : log1pf(expf(raw));
        sdt[tid] = sp;
        sdA[tid] = expf(sp * Aneg);
    }
    __syncthreads();

    for (int idx = tid; idx < CS * 80; idx += 256) {
        int s = idx / 80, ch = idx % 80;
        float v = scb[ch];
        #pragma unroll
        for (int k = 0; k < 4; k++) v += szx[s + k][ch] * scw[ch * 4 + k];
        v = siluf(v);
        if (ch < 64) sx[s][ch] = v; else sB[s][ch - 64] = v;
    }
    __syncthreads();

    float h0 = 0.f, h1 = 0.f, h2 = 0.f, h3 = 0.f;
    #pragma unroll 4
    for (int s = 0; s < CS; s++) {
        float dA = sdA[s];
        float coef = sdt[s] * sx[s][p];
        float4 Bv = *(const float4*)&sB[s][q * 4];
        h0 = h0 * dA + coef * Bv.x;
        h1 = h1 * dA + coef * Bv.y;
        h2 = h2 * dA + coef * Bv.z;
        h3 = h3 * dA + coef * Bv.w;
    }
    size_t base = (((size_t)(b * NHEADS + h) * NC + c) << 10) + tid * 4;
    *(float4*)&g_hstate[dir][base] = make_float4(h0, h1, h2, h3);
    if (tid == 0) {
        float P = 1.f;
        for (int s = 0; s < CS; s++) P *= sdA[s];
        g_P[dir][(b * NHEADS + h) * NC + c] = P;
    }
}

// ======== chunked scan: middle combine ==========================================
__global__ void __launch_bounds__(256)
scanMid_kernel()
{
    const int h = blockIdx.x, b = blockIdx.y, dir = blockIdx.z;
    const int tid = threadIdx.x;
    float* hs = g_hstate[dir];
    const size_t base = ((size_t)(b * NHEADS + h) * NC << 10) + tid * 4;
    __shared__ float sP[NC];
    if (tid < NC) sP[tid] = g_P[dir][(b * NHEADS + h) * NC + tid];
    __syncthreads();
    float4 nxt = *(float4*)&hs[base];
    float4 run = make_float4(0.f, 0.f, 0.f, 0.f);
    for (int c = 0; c < NC; c++) {
        float4 endv = nxt;
        if (c + 1 < NC) nxt = *(float4*)&hs[base + ((size_t)(c + 1) << 10)];
        *(float4*)&hs[base + ((size_t)c << 10)] = run;
        float P = sP[c];
        run.x = P * run.x + endv.x;
        run.y = P * run.y + endv.y;
        run.z = P * run.z + endv.z;
        run.w = P * run.w + endv.w;
    }
}

// ======== fused conv + chunked scan pass B (seeded, emit y) =====================
#define SB_SMEM ((67 * 96 + 64 * 64 + 1024 + 1024 + 64 + 64 + 384 + 96) * 4)

__global__ void __launch_bounds__(256)
scanB_kernel(const float* __restrict__ Al0, const float* __restrict__ Al1,
             const float* __restrict__ Dp0, const float* __restrict__ Dp1,
             const float* __restrict__ cw0, const float* __restrict__ cw1,
             const float* __restrict__ cb0, const float* __restrict__ cb1,
             const float* __restrict__ db0, const float* __restrict__ db1)
{
    extern __shared__ float sm[];
    float* szx = sm;                       // [67][96]
    float* sx  = sm + 67 * 96;             // [64][64]
    float* sB  = sx + 64 * 64;             // [64][16]
    float* sC  = sB + 1024;                // [64][16]
    float* sdt = sC + 1024;                // [64]
    float* sdA = sdt + 64;                 // [64]
    float* scw = sdA + 64;                 // [96*4]
    float* scb = scw + 384;                // [96]
    float* sy  = szx;                      // reuse after conv phase

    const int c = blockIdx.x, h = blockIdx.y;
    const int b = blockIdx.z & (B_SZ - 1), dir = blockIdx.z >> 3;
    const int tid = threadIdx.x;
    const int p = tid >> 2, q = tid & 3;
    const float Aneg = -expf((dir ? Al1 : Al0)[h]);
    const float Dh = (dir ? Dp1 : Dp0)[h];
    const float* conv_w  = dir ? cw1 : cw0;
    const float* conv_b  = dir ? cb1 : cb0;
    const float* dt_bias = dir ? db1 : db0;
    const __half* zx = g_zx16[dir];

    const int l0 = c * CS;
    const size_t rowbase = (size_t)b * L_SEQ + l0;

    for (int idx = tid; idx < (CS + 3) * 96; idx += 256) {
        int s = idx / 96, ch = idx % 96;
        int ll = l0 + s - 3;
        int zc = (ch < 64) ? (D_INNER + h * 64 + ch) : (D_INNER + 1024 + (ch - 64));
        szx[s * 96 + ch] = (ll >= 0)
            ? __half2float(zx[((size_t)b * L_SEQ + ll) * D_IN_PROJ + zc]) : 0.f;
    }
    if (tid < 96) {
        int cc = (tid < 64) ? (h * 64 + tid) : (1024 + (tid - 64));
        scb[tid] = conv_b[cc];
        #pragma unroll
        for (int k = 0; k < 4; k++) scw[tid * 4 + k] = conv_w[cc * 4 + k];
    }
    if (tid < CS) {
        float raw = g_dtraw[dir][(rowbase + tid) * 16 + h] + dt_bias[h];
        float sp = (raw > 20.f) ? raw : log1pf(expf(raw));
        sdt[tid] = sp;
        sdA[tid] = expf(sp * Aneg);
    }
    float4 hin = *(float4*)&g_hstate[dir][(((size_t)(b * NHEADS + h) * NC + c) << 10) + tid * 4];
    __syncthreads();

    for (int idx = tid; idx < CS * 96; idx += 256) {
        int s = idx / 96, ch = idx % 96;
        float v = scb[ch];
        #pragma unroll
        for (int k = 0; k < 4; k++) v += szx[(s + k) * 96 + ch] * scw[ch * 4 + k];
        v = siluf(v);
        if (ch < 64) sx[s * 64 + ch] = v;
        else if (ch < 80) sB[s * 16 + (ch - 64)] = v;
        else sC[s * 16 + (ch - 80)] = v;
    }
    __syncthreads();

    float h0 = hin.x, h1 = hin.y, h2 = hin.z, h3 = hin.w;
    for (int s = 0; s < CS; s++) {
        float dA = sdA[s];
        float xv = sx[s * 64 + p];
        float coef = sdt[s] * xv;
        float4 Bv = *(const float4*)&sB[s * 16 + q * 4];
        float4 Cv = *(const float4*)&sC[s * 16 + q * 4];
        h0 = h0 * dA + coef * Bv.x;
        h1 = h1 * dA + coef * Bv.y;
        h2 = h2 * dA + coef * Bv.z;
        h3 = h3 * dA + coef * Bv.w;
        float yp = h0 * Cv.x + h1 * Cv.y + h2 * Cv.z + h3 * Cv.w;
        yp += __shfl_xor_sync(0xffffffffu, yp, 1);
        yp += __shfl_xor_sync(0xffffffffu, yp, 2);
        if (q == 0) sy[s * 64 + p] = yp + Dh * xv;
    }
    __syncthreads();
    for (int idx = tid; idx < CS * 64; idx += 256) {
        int s = idx >> 6, pp = idx & 63;
        g_y[dir][(rowbase + s) * D_INNER + h * 64 + pp] = sy[s * 64 + pp];
    }
}

// ------- y *= silu(z); RMSNorm(y) * norm_w; emit fp16 for combined GEMM ----------
__global__ void gate_rms_kernel(const float* __restrict__ nw0, const float* __restrict__ nw1)
{
    const int row = blockIdx.x, dir = blockIdx.y, tid = threadIdx.x;
    const float* norm_w = dir ? nw1 : nw0;
    const float* yp = &g_y[dir][(size_t)row * D_INNER + tid * 4];
    const __half2* zp = (const __half2*)&g_zx16[dir][(size_t)row * D_IN_PROJ + tid * 4];
    float4 yv = *(const float4*)yp;
    float2 z01 = __half22float2(zp[0]);
    float2 z23 = __half22float2(zp[1]);
    yv.x *= siluf(z01.x);
    yv.y *= siluf(z01.y);
    yv.z *= siluf(z23.x);
    yv.w *= siluf(z23.y);
    float ss = yv.x * yv.x + yv.y * yv.y + yv.z * yv.z + yv.w * yv.w;
    __shared__ float red[8];
    #pragma unroll
    for (int o = 16; o > 0; o >>= 1) ss += __shfl_xor_sync(0xffffffffu, ss, o);
    if ((tid & 31) == 0) red[tid >> 5] = ss;
    __syncthreads();
    float tot = red[0] + red[1] + red[2] + red[3] + red[4] + red[5] + red[6] + red[7];
    float sc = rsqrtf(tot * (1.f / D_INNER) + 1e-5f);
    float4 nv = *(const float4*)&norm_w[tid * 4];
    __half2* hp = (__half2*)&g_y16[dir][(size_t)row * D_INNER + tid * 4];
    hp[0] = __floats2half2_rn(yv.x * sc * nv.x, yv.y * sc * nv.y);
    hp[1] = __floats2half2_rn(yv.z * sc * nv.z, yv.w * sc * nv.w);
}

// ---------------- final LayerNorm over 512 -> d_out ------------------------------
__global__ void ln_kernel(const float* __restrict__ ln_w, const float* __restrict__ ln_b,
                          float* __restrict__ out)
{
    const int row = blockIdx.x, tid = threadIdx.x;  // 128 threads
    const size_t base = (size_t)row * D_MODEL;
    float4 v = *(const float4*)&g_pre[base + tid * 4];
    float s = v.x + v.y + v.z + v.w;
    float s2 = v.x * v.x + v.y * v.y + v.z * v.z + v.w * v.w;
    __shared__ float rs[4], rs2[4];
    #pragma unroll
    for (int o = 16; o > 0; o >>= 1) {
        s  += __shfl_xor_sync(0xffffffffu, s, o);
        s2 += __shfl_xor_sync(0xffffffffu, s2, o);
    }
    if ((tid & 31) == 0) { rs[tid >> 5] = s; rs2[tid >> 5] = s2; }
    __syncthreads();
    float ts = rs[0] + rs[1] + rs[2] + rs[3];
    float ts2 = rs2[0] + rs2[1] + rs2[2] + rs2[3];
    float mu = ts * (1.f / D_MODEL);
    float var = ts2 * (1.f / D_MODEL) - mu * mu;
    float isd = rsqrtf(var + 1e-5f);
    float4 wv = *(const float4*)&ln_w[tid * 4];
    float4 bv = *(const float4*)&ln_b[tid * 4];
    float4 o;
    o.x = (v.x - mu) * isd * wv.x + bv.x;
    o.y = (v.y - mu) * isd * wv.y + bv.y;
    o.z = (v.z - mu) * isd * wv.z + bv.z;
    o.w = (v.w - mu) * isd * wv.w + bv.w;
    *(float4*)&out[base + tid * 4] = o;
}

// ---------------- orchestration ---------------------------------------------------
extern "C" void kernel_launch(void* const* d_in, const int* in_sizes, int n_in,
                              void* d_out, int out_size)
{
    const float* x      = (const float*)d_in[0];
    const float* f_in_proj  = (const float*)d_in[1];
    const float* f_conv_w   = (const float*)d_in[2];
    const float* f_conv_b   = (const float*)d_in[3];
    const float* f_dt_bias  = (const float*)d_in[4];
    const float* f_A_log    = (const float*)d_in[5];
    const float* f_D        = (const float*)d_in[6];
    const float* f_norm_w   = (const float*)d_in[7];
    const float* f_out_proj = (const float*)d_in[8];
    const float* b_in_proj  = (const float*)d_in[9];
    const float* b_conv_w   = (const float*)d_in[10];
    const float* b_conv_b   = (const float*)d_in[11];
    const float* b_dt_bias  = (const float*)d_in[12];
    const float* b_A_log    = (const float*)d_in[13];
    const float* b_D        = (const float*)d_in[14];
    const float* b_norm_w   = (const float*)d_in[15];
    const float* b_out_proj = (const float*)d_in[16];
    const float* proj_w = (const float*)d_in[17];
    const float* proj_b = (const float*)d_in[18];
    const float* ln_w   = (const float*)d_in[19];
    const float* ln_b   = (const float*)d_in[20];

    float *pre, *dtraw;
    __half *zx16, *x16, *wip16, *wpr16, *wofT16, *wcomb16, *y16;
    cudaGetSymbolAddress((void**)&zx16, g_zx16);
    cudaGetSymbolAddress((void**)&dtraw, g_dtraw);
    cudaGetSymbolAddress((void**)&pre, g_pre);
    cudaGetSymbolAddress((void**)&x16, g_x16);
    cudaGetSymbolAddress((void**)&wip16, g_wip16);
    cudaGetSymbolAddress((void**)&wpr16, g_wpr16);
    cudaGetSymbolAddress((void**)&wofT16, g_wofT16);
    cudaGetSymbolAddress((void**)&wcomb16, g_wcomb16);
    cudaGetSymbolAddress((void**)&y16, g_y16);

    cudaFuncSetAttribute(gemm_f16, cudaFuncAttributeMaxDynamicSharedMemorySize, GT_SMEM);
    cudaFuncSetAttribute(scanB_kernel, cudaFuncAttributeMaxDynamicSharedMemorySize, SB_SMEM);

    // fp32 -> fp16 conversions + out_proj transposes
    f2h_kernel<<<2048, 256>>>(x, x16, BL * D_MODEL / 4);
    f2h_kernel<<<256, 256>>>(f_in_proj, wip16, D_IN_PROJ * D_MODEL / 4);
    f2h_kernel<<<256, 256>>>(b_in_proj, wip16 + (size_t)D_IN_PROJ * D_MODEL,
                             D_IN_PROJ * D_MODEL / 4);
    f2h_kernel<<<128, 256>>>(proj_w, wpr16, D_MODEL * D_INNER / 4);
    tr_f2h_kernel<<<dim3(32, 16, 2), dim3(32, 8)>>>(
        f_out_proj, b_out_proj, wofT16, wofT16 + (size_t)D_INNER * D_MODEL);

    // weight combine: wcomb[m][k + dir*1024] = sum_n proj_w[m][n + dir*512] * out_proj_dir[n][k]
    gemm_f16<<<dim3(D_INNER / 128, D_MODEL / 128, 2), 256, GT_SMEM>>>(
        wpr16, wpr16 + 512, D_INNER,
        wofT16, wofT16 + (size_t)D_INNER * D_MODEL, D_MODEL,
        wcomb16, wcomb16, 2 * D_INNER, D_INNER,
        D_INNER, D_MODEL, D_MODEL, 0, 0, 1, nullptr, nullptr, nullptr, 0);

    // in_proj both dirs: zx16[z] = x16(flip if z) @ wip16[z]^T  -> fp16 + fp32 dt aux
    gemm_f16<<<dim3((D_IN_PROJ + 127) / 128, BL / 128, 2), 256, GT_SMEM>>>(
        x16, x16, D_MODEL, wip16, wip16 + (size_t)D_IN_PROJ * D_MODEL, D_MODEL,
        zx16, zx16 + (size_t)BL * D_IN_PROJ, D_IN_PROJ, 0,
        D_IN_PROJ, D_MODEL, D_MODEL, 0b10, 0, 1, nullptr, nullptr,
        dtraw, D_INNER + CONV_DIM);

    // fused conv + scan
    scanA_kernel<<<dim3(NC, NHEADS, 2 * B_SZ), 256>>>(
        f_A_log, b_A_log, f_conv_w, b_conv_w, f_conv_b, b_conv_b, f_dt_bias, b_dt_bias);
    scanMid_kernel<<<dim3(NHEADS, B_SZ, 2), 256>>>();
    scanB_kernel<<<dim3(NC, NHEADS, 2 * B_SZ), 256, SB_SMEM>>>(
        f_A_log, b_A_log, f_D, b_D,
        f_conv_w, b_conv_w, f_conv_b, b_conv_b, f_dt_bias, b_dt_bias);

    gate_rms_kernel<<<dim3(BL, 2), 256>>>(f_norm_w, b_norm_w);

    // combined projection: pre = x + proj_b + [y_f | y_b(flip)] @ wcomb^T  (K=2048)
    gemm_f16<<<dim3(D_MODEL / 128, BL / 128, 1), 256, GT_SMEM>>>(
        y16, y16 + (size_t)BL * D_INNER, D_INNER,
        wcomb16, wcomb16, 2 * D_INNER,
        pre, pre, D_MODEL, 0,
        D_MODEL, 2 * D_INNER, D_INNER, 0b10, 0, 0, proj_b, x,
        nullptr, 0);

    ln_kernel<<<BL, 128>>>(ln_w, ln_b, (float*)d_out);
}